// round 10
// baseline (speedup 1.0000x reference)
#include <cuda_runtime.h>
#include <cstdint>

// Problem constants
#define NB 32
#define SEQ 64
#define EMB 512
#define NH 4
#define NTOK (NB*SEQ)          // 2048
#define NBIG 1792              // 1536 (qkv) + 128 (d1W1) + 128 (d2W1)

// ---------------- device scratch (no runtime alloc allowed) ----------------
__device__ float g_big  [NTOK*NBIG];     // qkv | y1 | y2
__device__ float g_wbig [NBIG*EMB];
__device__ float g_bbig [NBIG];
__device__ float g_attn [NB*NH*SEQ*SEQ];
__device__ float g_xres [NTOK*1024];     // [x1 | attno]
__device__ float g_h    [NTOK*EMB];
__device__ float g_ln1  [NTOK*EMB];
__device__ float g_h2   [NTOK*EMB];
__device__ float g_M    [EMB*EMB];       // M = W1b @ Wo
__device__ float g_b1p  [EMB];           // b1 + W1b @ bo

// ---------------- packed-fp32 helpers (FFMA2 via PTX) -----------------------
__device__ __forceinline__ unsigned long long ffma2(
    unsigned long long a, unsigned long long b, unsigned long long c)
{
    unsigned long long d;
    asm("fma.rn.f32x2 %0, %1, %2, %3;" : "=l"(d) : "l"(a), "l"(b), "l"(c));
    return d;
}
__device__ __forceinline__ unsigned long long bcast2(float x)
{
    unsigned long long d;
    asm("mov.b64 %0, {%1, %1};" : "=l"(d) : "f"(x));
    return d;
}
__device__ __forceinline__ void unpack2(unsigned long long d, float& lo, float& hi)
{
    asm("mov.b64 {%0, %1}, %2;" : "=f"(lo), "=f"(hi) : "l"(d));
}
__device__ __forceinline__ float hsum2(unsigned long long d)
{
    float lo, hi;
    asm("mov.b64 {%0, %1}, %2;" : "=f"(lo), "=f"(hi) : "l"(d));
    return lo + hi;
}

// ---- bias assembly: bqkv | zeros(256) --------------------------------------
__global__ void pack_bias_kernel(const float* __restrict__ bqkv, float* __restrict__ bbig)
{
    int i = blockIdx.x*256 + threadIdx.x;
    if (i < NBIG) bbig[i] = (i < 1536) ? bqkv[i] : 0.f;
}

// ---- b1p[n] = b1[n] + sum_j W1b[n][j]*bo[j] --------------------------------
// grid 128 x 128 threads; warp w of block b handles n = b*4 + w.
__global__ void __launch_bounds__(128) b1p_kernel(
    const float* __restrict__ W1, const float* __restrict__ b1,
    const float* __restrict__ bo, float* __restrict__ b1p)
{
    int w = threadIdx.x >> 5, lane = threadIdx.x & 31;
    int n = blockIdx.x*4 + w;
    const float* row = W1 + (size_t)n*1024 + 512;
    float s = 0.f;
    #pragma unroll
    for (int j = 0; j < 16; j++) {
        int c = lane + j*32;
        s = fmaf(row[c], bo[c], s);
    }
    for (int o = 16; o; o >>= 1) s += __shfl_xor_sync(0xffffffffu, s, o);
    if (lane == 0) b1p[n] = b1[n] + s;
}

// ---------------- big GEMM: BM=128, BN=128, BK=16, FFMA2 --------------------
__global__ void __launch_bounds__(256, 2) gemm_big(
    const float* __restrict__ A, int lda,
    const float* __restrict__ B, int ldb,
    float* __restrict__ C, int ldc,
    const float* __restrict__ bias, int K)
{
    __shared__ float As[2][16][128];
    __shared__ float Bs[2][16][128];
    int bm = blockIdx.y << 7, bn = blockIdx.x << 7;
    int tid = threadIdx.x;
    int ty = tid >> 4, tx = tid & 15;
    int lr = tid >> 2, lk = (tid & 3) << 2;

    const float* Ap0 = A + (size_t)(bm + lr) * lda + lk;
    const float* Ap1 = Ap0 + (size_t)64 * lda;
    const float* Bp0 = B + (size_t)(bn + lr) * ldb + lk;
    const float* Bp1 = Bp0 + (size_t)64 * ldb;

    unsigned long long acc[4][8];
    #pragma unroll
    for (int i = 0; i < 4; i++)
        #pragma unroll
        for (int j = 0; j < 8; j++) acc[i][j] = 0ull;

    {
        float4 a0 = *(const float4*)Ap0;
        float4 a1 = *(const float4*)Ap1;
        float4 b0 = *(const float4*)Bp0;
        float4 b1 = *(const float4*)Bp1;
        As[0][lk+0][lr]    = a0.x; As[0][lk+1][lr]    = a0.y;
        As[0][lk+2][lr]    = a0.z; As[0][lk+3][lr]    = a0.w;
        As[0][lk+0][lr+64] = a1.x; As[0][lk+1][lr+64] = a1.y;
        As[0][lk+2][lr+64] = a1.z; As[0][lk+3][lr+64] = a1.w;
        Bs[0][lk+0][lr]    = b0.x; Bs[0][lk+1][lr]    = b0.y;
        Bs[0][lk+2][lr]    = b0.z; Bs[0][lk+3][lr]    = b0.w;
        Bs[0][lk+0][lr+64] = b1.x; Bs[0][lk+1][lr+64] = b1.y;
        Bs[0][lk+2][lr+64] = b1.z; Bs[0][lk+3][lr+64] = b1.w;
    }
    __syncthreads();

    int nk = K >> 4;
    for (int c = 0; c < nk; ++c) {
        int cur = c & 1;
        float4 na0, na1, nb0, nb1;
        bool more = (c + 1 < nk);
        if (more) {
            int ko = (c + 1) << 4;
            na0 = *(const float4*)(Ap0 + ko);
            na1 = *(const float4*)(Ap1 + ko);
            nb0 = *(const float4*)(Bp0 + ko);
            nb1 = *(const float4*)(Bp1 + ko);
        }
        #pragma unroll
        for (int k = 0; k < 16; ++k) {
            ulonglong2 a01 = *(const ulonglong2*)&As[cur][k][ty*8];
            ulonglong2 a23 = *(const ulonglong2*)&As[cur][k][ty*8 + 4];
            float4 bf0 = *(const float4*)&Bs[cur][k][tx*8];
            float4 bf1 = *(const float4*)&Bs[cur][k][tx*8 + 4];
            unsigned long long ap[4] = {a01.x, a01.y, a23.x, a23.y};
            unsigned long long bd[8] = {bcast2(bf0.x), bcast2(bf0.y), bcast2(bf0.z), bcast2(bf0.w),
                                        bcast2(bf1.x), bcast2(bf1.y), bcast2(bf1.z), bcast2(bf1.w)};
            #pragma unroll
            for (int i = 0; i < 4; i++)
                #pragma unroll
                for (int j = 0; j < 8; j++)
                    acc[i][j] = ffma2(ap[i], bd[j], acc[i][j]);
        }
        if (more) {
            int nb = cur ^ 1;
            As[nb][lk+0][lr]    = na0.x; As[nb][lk+1][lr]    = na0.y;
            As[nb][lk+2][lr]    = na0.z; As[nb][lk+3][lr]    = na0.w;
            As[nb][lk+0][lr+64] = na1.x; As[nb][lk+1][lr+64] = na1.y;
            As[nb][lk+2][lr+64] = na1.z; As[nb][lk+3][lr+64] = na1.w;
            Bs[nb][lk+0][lr]    = nb0.x; Bs[nb][lk+1][lr]    = nb0.y;
            Bs[nb][lk+2][lr]    = nb0.z; Bs[nb][lk+3][lr]    = nb0.w;
            Bs[nb][lk+0][lr+64] = nb1.x; Bs[nb][lk+1][lr+64] = nb1.y;
            Bs[nb][lk+2][lr+64] = nb1.z; Bs[nb][lk+3][lr+64] = nb1.w;
            __syncthreads();
        }
    }

    int n0 = bn + tx*8;
    float bv[8] = {0,0,0,0,0,0,0,0};
    if (bias) {
        float4 t0 = *(const float4*)&bias[n0];
        float4 t1 = *(const float4*)&bias[n0 + 4];
        bv[0]=t0.x; bv[1]=t0.y; bv[2]=t0.z; bv[3]=t0.w;
        bv[4]=t1.x; bv[5]=t1.y; bv[6]=t1.z; bv[7]=t1.w;
    }
    #pragma unroll
    for (int i2 = 0; i2 < 4; i2++) {
        float r0[8], r1[8];
        #pragma unroll
        for (int j = 0; j < 8; j++) {
            unpack2(acc[i2][j], r0[j], r1[j]);
            r0[j] += bv[j]; r1[j] += bv[j];
        }
        int m0 = bm + ty*8 + i2*2;
        *(float4*)&C[(size_t)m0*ldc + n0]       = make_float4(r0[0],r0[1],r0[2],r0[3]);
        *(float4*)&C[(size_t)m0*ldc + n0 + 4]   = make_float4(r0[4],r0[5],r0[6],r0[7]);
        *(float4*)&C[(size_t)(m0+1)*ldc + n0]   = make_float4(r1[0],r1[1],r1[2],r1[3]);
        *(float4*)&C[(size_t)(m0+1)*ldc + n0+4] = make_float4(r1[4],r1[5],r1[6],r1[7]);
    }
}

// ---------------- GEMM: BM=128, BN=64, BK=16, FFMA2 -------------------------
// B rows are [n][k]; if B2 != nullptr, k >= 512 reads come from B2[n][k-512].
// mode 0: C = acc + bias ; mode 1: C = resid + relu(acc + bias)
__global__ void __launch_bounds__(256, 2) gemm_nt(
    const float* __restrict__ A, int lda,
    const float* __restrict__ B, int ldb,
    const float* __restrict__ B2, int ldb2,
    float* __restrict__ C, int ldc,
    const float* __restrict__ bias,
    const float* __restrict__ resid, int ldr,
    int K, int mode)
{
    __shared__ float As[2][16][128];
    __shared__ float Bs[2][16][64];
    int bm = blockIdx.y << 7, bn = blockIdx.x << 6;
    int tid = threadIdx.x;
    int ty = tid >> 4, tx = tid & 15;
    int lr = tid >> 2, lk = (tid & 3) << 2;

    const float* Ap0 = A + (size_t)(bm + lr) * lda + lk;
    const float* Ap1 = Ap0 + (size_t)64 * lda;

    unsigned long long acc[4][4];
    #pragma unroll
    for (int i = 0; i < 4; i++)
        #pragma unroll
        for (int j = 0; j < 4; j++) acc[i][j] = 0ull;

    {
        float4 a0 = *(const float4*)Ap0;
        float4 a1 = *(const float4*)Ap1;
        float4 b0 = *(const float4*)(B + (size_t)(bn + lr)*ldb + lk);
        As[0][lk+0][lr]    = a0.x; As[0][lk+1][lr]    = a0.y;
        As[0][lk+2][lr]    = a0.z; As[0][lk+3][lr]    = a0.w;
        As[0][lk+0][lr+64] = a1.x; As[0][lk+1][lr+64] = a1.y;
        As[0][lk+2][lr+64] = a1.z; As[0][lk+3][lr+64] = a1.w;
        Bs[0][lk+0][lr] = b0.x; Bs[0][lk+1][lr] = b0.y;
        Bs[0][lk+2][lr] = b0.z; Bs[0][lk+3][lr] = b0.w;
    }
    __syncthreads();

    int nk = K >> 4;
    for (int c = 0; c < nk; ++c) {
        int cur = c & 1;
        float4 na0, na1, nb0;
        bool more = (c + 1 < nk);
        if (more) {
            int ko = (c + 1) << 4;
            na0 = *(const float4*)(Ap0 + ko);
            na1 = *(const float4*)(Ap1 + ko);
            const float* bp;
            if (B2 && ko >= 512)
                bp = B2 + (size_t)(bn + lr)*ldb2 + (ko - 512) + lk;
            else
                bp = B + (size_t)(bn + lr)*ldb + ko + lk;
            nb0 = *(const float4*)bp;
        }
        #pragma unroll
        for (int k = 0; k < 16; ++k) {
            ulonglong2 a01 = *(const ulonglong2*)&As[cur][k][ty*8];
            ulonglong2 a23 = *(const ulonglong2*)&As[cur][k][ty*8 + 4];
            float4 bf = *(const float4*)&Bs[cur][k][tx*4];
            unsigned long long ap[4] = {a01.x, a01.y, a23.x, a23.y};
            unsigned long long bd[4] = {bcast2(bf.x), bcast2(bf.y), bcast2(bf.z), bcast2(bf.w)};
            #pragma unroll
            for (int i = 0; i < 4; i++)
                #pragma unroll
                for (int j = 0; j < 4; j++)
                    acc[i][j] = ffma2(ap[i], bd[j], acc[i][j]);
        }
        if (more) {
            int nb = cur ^ 1;
            As[nb][lk+0][lr]    = na0.x; As[nb][lk+1][lr]    = na0.y;
            As[nb][lk+2][lr]    = na0.z; As[nb][lk+3][lr]    = na0.w;
            As[nb][lk+0][lr+64] = na1.x; As[nb][lk+1][lr+64] = na1.y;
            As[nb][lk+2][lr+64] = na1.z; As[nb][lk+3][lr+64] = na1.w;
            Bs[nb][lk+0][lr] = nb0.x; Bs[nb][lk+1][lr] = nb0.y;
            Bs[nb][lk+2][lr] = nb0.z; Bs[nb][lk+3][lr] = nb0.w;
            __syncthreads();
        }
    }

    int n = bn + tx*4;
    float4 bv = make_float4(0.f,0.f,0.f,0.f);
    if (bias) bv = *(const float4*)&bias[n];
    #pragma unroll
    for (int i2 = 0; i2 < 4; i2++) {
        float r0[4], r1[4];
        #pragma unroll
        for (int j = 0; j < 4; j++) unpack2(acc[i2][j], r0[j], r1[j]);
        int m0 = bm + ty*8 + i2*2;
        float4 v0 = make_float4(r0[0]+bv.x, r0[1]+bv.y, r0[2]+bv.z, r0[3]+bv.w);
        float4 v1 = make_float4(r1[0]+bv.x, r1[1]+bv.y, r1[2]+bv.z, r1[3]+bv.w);
        if (mode == 1) {
            float4 ra = *(const float4*)&resid[(size_t)m0*ldr + n];
            float4 rb = *(const float4*)&resid[(size_t)(m0+1)*ldr + n];
            v0.x = ra.x + fmaxf(v0.x,0.f); v0.y = ra.y + fmaxf(v0.y,0.f);
            v0.z = ra.z + fmaxf(v0.z,0.f); v0.w = ra.w + fmaxf(v0.w,0.f);
            v1.x = rb.x + fmaxf(v1.x,0.f); v1.y = rb.y + fmaxf(v1.y,0.f);
            v1.z = rb.z + fmaxf(v1.z,0.f); v1.w = rb.w + fmaxf(v1.w,0.f);
        }
        *(float4*)&C[(size_t)m0*ldc + n]     = v0;
        *(float4*)&C[(size_t)(m0+1)*ldc + n] = v1;
    }
}

// ---------------- NN GEMM: C[m][n] = sum_j A[m][j] * B[j][n] ----------------
// BM=128, BN=64, BK=16.  Used for M = W1b @ Wo.
__global__ void __launch_bounds__(256, 2) gemm_nn(
    const float* __restrict__ A, int lda,
    const float* __restrict__ B, int ldb,
    float* __restrict__ C, int ldc, int K)
{
    __shared__ float As[2][16][128];
    __shared__ float Bs[2][16][64];
    int bm = blockIdx.y << 7, bn = blockIdx.x << 6;
    int tid = threadIdx.x;
    int ty = tid >> 4, tx = tid & 15;
    int lr = tid >> 2, lk = (tid & 3) << 2;
    int jr = tid >> 4, ncl = (tid & 15) << 2;

    const float* Ap0 = A + (size_t)(bm + lr) * lda + lk;
    const float* Ap1 = Ap0 + (size_t)64 * lda;
    const float* Bp  = B + (size_t)jr * ldb + bn + ncl;

    unsigned long long acc[4][4];
    #pragma unroll
    for (int i = 0; i < 4; i++)
        #pragma unroll
        for (int j = 0; j < 4; j++) acc[i][j] = 0ull;

    {
        float4 a0 = *(const float4*)Ap0;
        float4 a1 = *(const float4*)Ap1;
        float4 b0 = *(const float4*)Bp;
        As[0][lk+0][lr]    = a0.x; As[0][lk+1][lr]    = a0.y;
        As[0][lk+2][lr]    = a0.z; As[0][lk+3][lr]    = a0.w;
        As[0][lk+0][lr+64] = a1.x; As[0][lk+1][lr+64] = a1.y;
        As[0][lk+2][lr+64] = a1.z; As[0][lk+3][lr+64] = a1.w;
        *(float4*)&Bs[0][jr][ncl] = b0;
    }
    __syncthreads();

    int nk = K >> 4;
    for (int c = 0; c < nk; ++c) {
        int cur = c & 1;
        float4 na0, na1, nb0;
        bool more = (c + 1 < nk);
        if (more) {
            int ko = (c + 1) << 4;
            na0 = *(const float4*)(Ap0 + ko);
            na1 = *(const float4*)(Ap1 + ko);
            nb0 = *(const float4*)(Bp + (size_t)ko * ldb);
        }
        #pragma unroll
        for (int k = 0; k < 16; ++k) {
            ulonglong2 a01 = *(const ulonglong2*)&As[cur][k][ty*8];
            ulonglong2 a23 = *(const ulonglong2*)&As[cur][k][ty*8 + 4];
            float4 bf = *(const float4*)&Bs[cur][k][tx*4];
            unsigned long long ap[4] = {a01.x, a01.y, a23.x, a23.y};
            unsigned long long bd[4] = {bcast2(bf.x), bcast2(bf.y), bcast2(bf.z), bcast2(bf.w)};
            #pragma unroll
            for (int i = 0; i < 4; i++)
                #pragma unroll
                for (int j = 0; j < 4; j++)
                    acc[i][j] = ffma2(ap[i], bd[j], acc[i][j]);
        }
        if (more) {
            int nb = cur ^ 1;
            As[nb][lk+0][lr]    = na0.x; As[nb][lk+1][lr]    = na0.y;
            As[nb][lk+2][lr]    = na0.z; As[nb][lk+3][lr]    = na0.w;
            As[nb][lk+0][lr+64] = na1.x; As[nb][lk+1][lr+64] = na1.y;
            As[nb][lk+2][lr+64] = na1.z; As[nb][lk+3][lr+64] = na1.w;
            *(float4*)&Bs[nb][jr][ncl] = nb0;
            __syncthreads();
        }
    }

    int n = bn + tx*4;
    #pragma unroll
    for (int i2 = 0; i2 < 4; i2++) {
        float r0[4], r1[4];
        #pragma unroll
        for (int j = 0; j < 4; j++) unpack2(acc[i2][j], r0[j], r1[j]);
        int m0 = bm + ty*8 + i2*2;
        *(float4*)&C[(size_t)m0*ldc + n]     = make_float4(r0[0],r0[1],r0[2],r0[3]);
        *(float4*)&C[(size_t)(m0+1)*ldc + n] = make_float4(r1[0],r1[1],r1[2],r1[3]);
    }
}

// -------- x1 path: Gram (FFMA2 over e) -> softmax -> x1 = attn @ x ----------
__global__ void __launch_bounds__(256) x1_kernel(
    const float* __restrict__ x, float* __restrict__ a_out, float* __restrict__ xres)
{
    extern __shared__ float sm[];
    const int STR = 516;
    float* xs   = sm;                    // 64*516
    float* sa   = xs + 64*STR;           // 32*64 local attn rows
    float* snrm = sa + 32*64;            // 64 norms
    int b = blockIdx.x >> 1, half = blockIdx.x & 1;
    int tid = threadIdx.x;
    const float4* xb4 = (const float4*)(x + (size_t)b*SEQ*EMB);
    for (int i = tid; i < SEQ*128; i += 256) {
        int r = i >> 7, c4 = i & 127;
        *(float4*)&xs[r*STR + 4*c4] = xb4[i];
    }
    __syncthreads();

    {
        int t = tid >> 2, sub = tid & 3;
        float s = 0.f;
        #pragma unroll 8
        for (int j = 0; j < 128; j++) {
            float v = xs[t*STR + sub + 4*j];
            s = fmaf(v, v, s);
        }
        s += __shfl_xor_sync(0xffffffffu, s, 1);
        s += __shfl_xor_sync(0xffffffffu, s, 2);
        if (sub == 0) snrm[t] = s;
    }

    int w = tid>>5, lane = tid&31;
    int fl0 = w*4;
    int fbase = half*32;

    unsigned long long p0[4] = {0,0,0,0}, p1[4] = {0,0,0,0};
    for (int e4 = 0; e4 < 128; e4++) {
        ulonglong2 g0 = *(const ulonglong2*)&xs[lane*STR + 4*e4];
        ulonglong2 g1 = *(const ulonglong2*)&xs[(lane+32)*STR + 4*e4];
        #pragma unroll
        for (int i = 0; i < 4; i++) {
            ulonglong2 fv = *(const ulonglong2*)&xs[(fbase+fl0+i)*STR + 4*e4];
            p0[i] = ffma2(fv.x, g0.x, p0[i]);
            p0[i] = ffma2(fv.y, g0.y, p0[i]);
            p1[i] = ffma2(fv.x, g1.x, p1[i]);
            p1[i] = ffma2(fv.y, g1.y, p1[i]);
        }
    }
    #pragma unroll
    for (int i = 0; i < 4; i++) {
        sa[(fl0+i)*64 + lane]      = hsum2(p0[i]);
        sa[(fl0+i)*64 + lane + 32] = hsum2(p1[i]);
    }
    __syncthreads();

    const float invT = 1.f/13.544f;
    float* ab = a_out + (size_t)b*4096;
    #pragma unroll
    for (int i = 0; i < 4; i++) {
        int fl = fl0 + i, f = fbase + fl;
        float nf = snrm[f];
        float s0 = (2.f*sa[fl*64+lane]    - nf - snrm[lane])    * invT;
        float s1 = (2.f*sa[fl*64+lane+32] - nf - snrm[lane+32]) * invT;
        float m = fmaxf(s0, s1);
        for (int o = 16; o; o >>= 1) m = fmaxf(m, __shfl_xor_sync(0xffffffffu, m, o));
        float e0 = __expf(s0 - m), e1 = __expf(s1 - m);
        float sum = e0 + e1;
        for (int o = 16; o; o >>= 1) sum += __shfl_xor_sync(0xffffffffu, sum, o);
        float r = 1.f/sum; e0 *= r; e1 *= r;
        sa[fl*64+lane] = e0; sa[fl*64+lane+32] = e1;
        ab[f*64+lane] = e0;  ab[f*64+lane+32] = e1;
    }
    __syncwarp();

    for (int ec = 0; ec < 4; ec++) {
        float acc[4][4];
        #pragma unroll
        for (int i = 0; i < 4; i++) { acc[i][0]=acc[i][1]=acc[i][2]=acc[i][3]=0.f; }
        for (int g4 = 0; g4 < 16; g4++) {
            float sarr[4][4];
            #pragma unroll
            for (int i = 0; i < 4; i++)
                *(float4*)sarr[i] = *(const float4*)&sa[(fl0+i)*64 + 4*g4];
            #pragma unroll
            for (int jj = 0; jj < 4; jj++) {
                int g = 4*g4 + jj;
                float vv[4];
                #pragma unroll
                for (int j = 0; j < 4; j++) vv[j] = xs[g*STR + ec*128 + j*32 + lane];
                #pragma unroll
                for (int i = 0; i < 4; i++)
                    #pragma unroll
                    for (int j = 0; j < 4; j++)
                        acc[i][j] = fmaf(sarr[i][jj], vv[j], acc[i][j]);
            }
        }
        #pragma unroll
        for (int i = 0; i < 4; i++)
            #pragma unroll
            for (int j = 0; j < 4; j++)
                xres[(size_t)(b*SEQ + fbase + fl0 + i)*1024 + ec*128 + j*32 + lane] = acc[i][j];
    }
}

// -------------- MHA core: QK^T (FFMA2 over e), softmax, AV ------------------
// Output written at out[token*ostride + h*128 + col] (directly into xres).
__global__ void __launch_bounds__(256) mha_kernel(
    const float* __restrict__ qkv, float* __restrict__ attn_g,
    float* __restrict__ outp, int ostride)
{
    extern __shared__ float sm[];
    const int STR = 132;
    float* qs = sm;
    float* ks = qs + 64*STR;
    float* vs = ks + 64*STR;
    float* sa = vs + 64*STR;
    int b = blockIdx.x >> 2, h = blockIdx.x & 3;
    int tid = threadIdx.x;
    const float* base = qkv + (size_t)b*SEQ*NBIG + h*128;
    for (int i = tid; i < 64*32; i += 256) {
        int r = i >> 5, c4 = (i & 31) << 2;
        const float* rp = base + (size_t)r*NBIG;
        *(float4*)&qs[r*STR+c4] = *(const float4*)&rp[c4];
        *(float4*)&ks[r*STR+c4] = *(const float4*)&rp[512 + c4];
        *(float4*)&vs[r*STR+c4] = *(const float4*)&rp[1024 + c4];
    }
    __syncthreads();
    int w = tid>>5, lane = tid&31, f0 = w*8;

    unsigned long long p0[8], p1[8];
    #pragma unroll
    for (int i = 0; i < 8; i++) { p0[i] = 0ull; p1[i] = 0ull; }
    for (int e4 = 0; e4 < 32; e4++) {
        ulonglong2 k0 = *(const ulonglong2*)&ks[lane*STR + 4*e4];
        ulonglong2 k1 = *(const ulonglong2*)&ks[(lane+32)*STR + 4*e4];
        #pragma unroll
        for (int i = 0; i < 8; i++) {
            ulonglong2 qv = *(const ulonglong2*)&qs[(f0+i)*STR + 4*e4];
            p0[i] = ffma2(qv.x, k0.x, p0[i]);
            p0[i] = ffma2(qv.y, k0.y, p0[i]);
            p1[i] = ffma2(qv.x, k1.x, p1[i]);
            p1[i] = ffma2(qv.y, k1.y, p1[i]);
        }
    }
    const float scale = 0.088388347648318447f;
    float* ab = attn_g + (size_t)(b*4 + h)*4096;
    #pragma unroll
    for (int i = 0; i < 8; i++) {
        float s0 = hsum2(p0[i])*scale, s1 = hsum2(p1[i])*scale;
        float m = fmaxf(s0, s1);
        for (int o = 16; o; o >>= 1) m = fmaxf(m, __shfl_xor_sync(0xffffffffu, m, o));
        float e0 = __expf(s0 - m), e1 = __expf(s1 - m);
        float sum = e0 + e1;
        for (int o = 16; o; o >>= 1) sum += __shfl_xor_sync(0xffffffffu, sum, o);
        float r = 1.f/sum; e0 *= r; e1 *= r;
        int f = f0 + i;
        sa[f*64+lane] = e0; sa[f*64+lane+32] = e1;
        ab[f*64+lane] = e0; ab[f*64+lane+32] = e1;
    }
    __syncwarp();
    float acc[8][4];
    #pragma unroll
    for (int i = 0; i < 8; i++) { acc[i][0]=acc[i][1]=acc[i][2]=acc[i][3]=0.f; }
    for (int g4 = 0; g4 < 16; g4++) {
        float sarr[8][4];
        #pragma unroll
        for (int i = 0; i < 8; i++)
            *(float4*)sarr[i] = *(const float4*)&sa[(f0+i)*64 + 4*g4];
        #pragma unroll
        for (int jj = 0; jj < 4; jj++) {
            int g = 4*g4 + jj;
            float vv[4];
            #pragma unroll
            for (int j = 0; j < 4; j++) vv[j] = vs[g*STR + j*32 + lane];
            #pragma unroll
            for (int i = 0; i < 8; i++)
                #pragma unroll
                for (int j = 0; j < 4; j++)
                    acc[i][j] = fmaf(sarr[i][jj], vv[j], acc[i][j]);
        }
    }
    #pragma unroll
    for (int i = 0; i < 8; i++)
        #pragma unroll
        for (int j = 0; j < 4; j++)
            outp[(size_t)(b*SEQ + f0 + i)*ostride + h*128 + j*32 + lane] = acc[i][j];
}

// ------------- layernorm over last dim (512) --------------------------------
__global__ void __launch_bounds__(128) ln_kernel(
    const float* __restrict__ in, const float* __restrict__ gw,
    const float* __restrict__ bw, float* __restrict__ out)
{
    int t = blockIdx.x, tid = threadIdx.x;
    const float* r = in + (size_t)t*EMB;
    float v[4];
    #pragma unroll
    for (int i = 0; i < 4; i++) v[i] = r[tid + i*128];
    float s  = v[0]+v[1]+v[2]+v[3];
    float s2 = v[0]*v[0]+v[1]*v[1]+v[2]*v[2]+v[3]*v[3];
    for (int o = 16; o; o >>= 1) {
        s  += __shfl_xor_sync(0xffffffffu, s,  o);
        s2 += __shfl_xor_sync(0xffffffffu, s2, o);
    }
    __shared__ float rs[4], rs2[4];
    int w = tid>>5, lane = tid&31;
    if (lane == 0) { rs[w] = s; rs2[w] = s2; }
    __syncthreads();
    s  = rs[0]+rs[1]+rs[2]+rs[3];
    s2 = rs2[0]+rs2[1]+rs2[2]+rs2[3];
    float mean = s*(1.f/512.f);
    float var  = s2*(1.f/512.f) - mean*mean;
    float inv  = rsqrtf(var + 1e-5f);
    #pragma unroll
    for (int i = 0; i < 4; i++) {
        int c = tid + i*128;
        out[(size_t)t*EMB + c] = (v[i]-mean)*inv*gw[c] + bw[c];
    }
}

// ------------- pair MLPs + fused head-mean ----------------------------------
__global__ void __launch_bounds__(256) pair_kernel(
    const float* __restrict__ ybig,
    const float* __restrict__ a1, const float* __restrict__ attn4,
    const float* __restrict__ b11, const float* __restrict__ w12, const float* __restrict__ b12,
    const float* __restrict__ b21, const float* __restrict__ w22, const float* __restrict__ b22,
    float* __restrict__ a2_out,
    float* __restrict__ o1, float* __restrict__ o2)
{
    extern __shared__ float sm[];
    float* sy1 = sm;            // 64*128
    float* sy2 = sy1 + 8192;    // 64*128
    float* sb1 = sy2 + 8192;
    float* sw1 = sb1 + 128;
    float* sb2 = sw1 + 128;
    float* sw2 = sb2 + 128;
    int b = blockIdx.x >> 2, q = blockIdx.x & 3;
    int tid = threadIdx.x;
    for (int i = tid; i < 8192; i += 256) {
        int r = i >> 7, c = i & 127;
        const float* rp = ybig + (size_t)(b*64 + r)*NBIG;
        sy1[i] = rp[1536 + c];
        sy2[i] = rp[1664 + c];
    }
    if (tid < 128) { sb1[tid]=b11[tid]; sw1[tid]=w12[tid]; sb2[tid]=b21[tid]; sw2[tid]=w22[tid]; }
    __syncthreads();
    float bias1 = b12[0], bias2 = b22[0];
    int w = tid>>5, lane = tid&31;
    int p0 = q*1024, p1 = p0 + 1024;
    const float* at = attn4 + (size_t)b*16384;
    for (int p = p0 + w; p < p1; p += 8) {
        int f = p >> 6, g = p & 63;
        float av1 = a1[(size_t)b*4096 + p];
        float av2 = 0.25f*(at[p] + at[p+4096] + at[p+8192] + at[p+12288]);
        const float* yg1 = sy1 + g*128; const float* yf1 = sy1 + f*128;
        const float* yg2 = sy2 + g*128; const float* yf2 = sy2 + f*128;
        float acc1 = 0.f, acc2 = 0.f;
        #pragma unroll
        for (int j = 0; j < 4; j++) {
            int c = j*32 + lane;
            float h1 = fmaf(av1, yg1[c]-yf1[c], sb1[c]);
            acc1 = fmaf(fmaxf(h1, 0.f), sw1[c], acc1);
            float h2 = fmaf(av2, yg2[c]-yf2[c], sb2[c]);
            acc2 = fmaf(fmaxf(h2, 0.f), sw2[c], acc2);
        }
        for (int o = 16; o; o >>= 1) {
            acc1 += __shfl_xor_sync(0xffffffffu, acc1, o);
            acc2 += __shfl_xor_sync(0xffffffffu, acc2, o);
        }
        if (lane == 0) {
            a2_out[(size_t)b*4096 + p] = av2;
            o1[(size_t)b*4096 + p] = fmaxf(acc1 + bias1, 0.f);
            o2[(size_t)b*4096 + p] = fmaxf(acc2 + bias2, 0.f);
        }
    }
}

// ---------------------------------------------------------------------------
extern "C" void kernel_launch(void* const* d_in, const int* in_sizes, int n_in,
                              void* d_out, int out_size)
{
    const float* x    = (const float*)d_in[0];
    const float* Wqkv = (const float*)d_in[1];
    const float* bqkv = (const float*)d_in[2];
    const float* Wo   = (const float*)d_in[3];
    const float* bo   = (const float*)d_in[4];
    const float* W1   = (const float*)d_in[5];
    const float* b1   = (const float*)d_in[6];
    const float* W2   = (const float*)d_in[7];
    const float* b2   = (const float*)d_in[8];
    const float* g1   = (const float*)d_in[9];
    const float* be1  = (const float*)d_in[10];
    const float* g2   = (const float*)d_in[11];
    const float* be2  = (const float*)d_in[12];
    const float* d1W1 = (const float*)d_in[13];
    const float* d1b1 = (const float*)d_in[14];
    const float* d1W2 = (const float*)d_in[15];
    const float* d1b2 = (const float*)d_in[16];
    const float* d2W1 = (const float*)d_in[17];
    const float* d2b1 = (const float*)d_in[18];
    const float* d2W2 = (const float*)d_in[19];
    const float* d2b2 = (const float*)d_in[20];

    float* out = (float*)d_out;
    float* A1 = out + 1048576;   // x1_attn (N,1,S,S)
    float* A2 = A1 + 131072;     // x2_attn
    float* D1 = A2 + 131072;     // diff1
    float* D2 = D1 + 131072;     // diff2

    float *p_big, *p_wbig, *p_bbig, *p_attn, *p_xres, *p_h, *p_ln1, *p_h2, *p_M, *p_b1p;
    cudaGetSymbolAddress((void**)&p_big,   g_big);
    cudaGetSymbolAddress((void**)&p_wbig,  g_wbig);
    cudaGetSymbolAddress((void**)&p_bbig,  g_bbig);
    cudaGetSymbolAddress((void**)&p_attn,  g_attn);
    cudaGetSymbolAddress((void**)&p_xres,  g_xres);
    cudaGetSymbolAddress((void**)&p_h,     g_h);
    cudaGetSymbolAddress((void**)&p_ln1,   g_ln1);
    cudaGetSymbolAddress((void**)&p_h2,    g_h2);
    cudaGetSymbolAddress((void**)&p_M,     g_M);
    cudaGetSymbolAddress((void**)&p_b1p,   g_b1p);

    const int X1_SMEM   = (64*516 + 32*64 + 64) * 4;  // 140544
    const int MHA_SMEM  = (3*64*132 + 4096) * 4;      // 117760
    const int PAIR_SMEM = (2*8192 + 4*128) * 4;       // 67584
    cudaFuncSetAttribute(x1_kernel,   cudaFuncAttributeMaxDynamicSharedMemorySize, X1_SMEM);
    cudaFuncSetAttribute(mha_kernel,  cudaFuncAttributeMaxDynamicSharedMemorySize, MHA_SMEM);
    cudaFuncSetAttribute(pair_kernel, cudaFuncAttributeMaxDynamicSharedMemorySize, PAIR_SMEM);

    static cudaStream_t s1 = nullptr, s2 = nullptr;
    static cudaEvent_t ev0, ev_x1, ev_mha, ev_pair, ev_m;
    if (!s1) {
        cudaStreamCreateWithFlags(&s1, cudaStreamNonBlocking);
        cudaStreamCreateWithFlags(&s2, cudaStreamNonBlocking);
        cudaEventCreateWithFlags(&ev0,     cudaEventDisableTiming);
        cudaEventCreateWithFlags(&ev_x1,   cudaEventDisableTiming);
        cudaEventCreateWithFlags(&ev_mha,  cudaEventDisableTiming);
        cudaEventCreateWithFlags(&ev_pair, cudaEventDisableTiming);
        cudaEventCreateWithFlags(&ev_m,    cudaEventDisableTiming);
    }

    // fork
    cudaEventRecord(ev0, 0);
    cudaStreamWaitEvent(s1, ev0, 0);
    cudaStreamWaitEvent(s2, ev0, 0);

    // branch s1: x1 path (depends only on x)
    x1_kernel<<<64, 256, X1_SMEM, s1>>>(x, A1, p_xres);
    cudaEventRecord(ev_x1, s1);

    // branch s2: weight-only precompute — M = W1b @ Wo, b1p = b1 + W1b@bo
    gemm_nn<<<dim3(8, 4), 256, 0, s2>>>(W1 + 512, 1024, Wo, 512, p_M, 512, 512);
    b1p_kernel<<<128, 128, 0, s2>>>(W1, b1, bo, p_b1p);
    cudaEventRecord(ev_m, s2);

    // main stream: pack weights -> merged projection -> MHA (writes xres[512:])
    cudaMemcpyAsync(p_wbig,            Wqkv, (size_t)1536*512*4, cudaMemcpyDeviceToDevice, 0);
    cudaMemcpyAsync(p_wbig + 1536*512, d1W1, (size_t)128*512*4,  cudaMemcpyDeviceToDevice, 0);
    cudaMemcpyAsync(p_wbig + 1664*512, d2W1, (size_t)128*512*4,  cudaMemcpyDeviceToDevice, 0);
    pack_bias_kernel<<<7, 256>>>(bqkv, p_bbig);
    gemm_big<<<dim3(NBIG/128, 16), 256>>>(x, 512, p_wbig, 512, p_big, NBIG, p_bbig, 512);
    mha_kernel<<<128, 256, MHA_SMEM>>>(p_big, p_attn, p_xres + 512, 1024);
    cudaEventRecord(ev_mha, 0);

    // branch s2: pair MLPs (+fused head-mean)
    cudaStreamWaitEvent(s2, ev_mha, 0);
    cudaStreamWaitEvent(s2, ev_x1, 0);
    pair_kernel<<<128, 256, PAIR_SMEM, s2>>>(p_big, A1, p_attn,
                                             d1b1, d1W2, d1b2, d2b1, d2W2, d2b2,
                                             A2, D1, D2);
    cudaEventRecord(ev_pair, s2);

    // main: fc1 with folded Wo  (B = W1 for k<512, B2 = M for k>=512)
    cudaStreamWaitEvent(0, ev_x1, 0);
    cudaStreamWaitEvent(0, ev_m, 0);
    gemm_nt<<<dim3(8, 16), 256>>>(p_xres, 1024, W1, 1024, p_M, 512,
                                  p_h, 512, p_b1p, x, 512, 1024, 1);
    ln_kernel<<<2048, 128>>>(p_h, g1, be1, p_ln1);
    gemm_nt<<<dim3(8, 16), 256>>>(p_ln1, 512, W2, 512, nullptr, 0,
                                  p_h2, 512, b2, p_ln1, 512, 512, 1);
    ln_kernel<<<2048, 128>>>(p_h2, g2, be2, out);

    // join s2
    cudaStreamWaitEvent(0, ev_pair, 0);
}

// round 12
// speedup vs baseline: 1.1896x; 1.1896x over previous
#include <cuda_runtime.h>
#include <cuda_bf16.h>
#include <cstdint>

// Problem constants
#define NB 32
#define SEQ 64
#define EMB 512
#define NH 4
#define NTOK (NB*SEQ)          // 2048
#define NBIG 1792              // 1536 (qkv) + 128 (d1W1) + 128 (d2W1)

// ---------------- device scratch (no runtime alloc allowed) ----------------
__device__ float g_big  [NTOK*NBIG];     // qkv | y1 | y2
__device__ float g_bbig [NBIG];
__device__ float g_attn [NB*NH*SEQ*SEQ];
__device__ float g_attno[NTOK*EMB];
__device__ float g_xres [NTOK*1024];
__device__ float g_h    [NTOK*EMB];
__device__ float g_ln1  [NTOK*EMB];
__device__ float g_h2   [NTOK*EMB];
__device__ __align__(16) __nv_bfloat16 g_xh[NTOK*EMB];
__device__ __align__(16) __nv_bfloat16 g_xl[NTOK*EMB];
__device__ __align__(16) __nv_bfloat16 g_wh[NBIG*EMB];
__device__ __align__(16) __nv_bfloat16 g_wl[NBIG*EMB];

// ---------------- packed-fp32 helpers (FFMA2 via PTX) -----------------------
__device__ __forceinline__ unsigned long long ffma2(
    unsigned long long a, unsigned long long b, unsigned long long c)
{
    unsigned long long d;
    asm("fma.rn.f32x2 %0, %1, %2, %3;" : "=l"(d) : "l"(a), "l"(b), "l"(c));
    return d;
}
__device__ __forceinline__ unsigned long long bcast2(float x)
{
    unsigned long long d;
    asm("mov.b64 %0, {%1, %1};" : "=l"(d) : "f"(x));
    return d;
}
__device__ __forceinline__ void unpack2(unsigned long long d, float& lo, float& hi)
{
    asm("mov.b64 {%0, %1}, %2;" : "=f"(lo), "=f"(hi) : "l"(d));
}
__device__ __forceinline__ float hsum2(unsigned long long d)
{
    float lo, hi;
    asm("mov.b64 {%0, %1}, %2;" : "=f"(lo), "=f"(hi) : "l"(d));
    return lo + hi;
}

// ---------------- mma.sync helpers ------------------------------------------
__device__ __forceinline__ uint32_t smem_u32(const void* p)
{
    uint32_t a;
    asm("{ .reg .u64 t; cvta.to.shared.u64 t, %1; cvt.u32.u64 %0, t; }" : "=r"(a) : "l"(p));
    return a;
}
__device__ __forceinline__ void ldsm4(uint32_t* r, uint32_t addr)
{
    asm volatile("ldmatrix.sync.aligned.m8n8.x4.shared.b16 {%0,%1,%2,%3}, [%4];"
        : "=r"(r[0]), "=r"(r[1]), "=r"(r[2]), "=r"(r[3]) : "r"(addr));
}
__device__ __forceinline__ void mma_bf16(float* d, const uint32_t* a, uint32_t b0, uint32_t b1)
{
    asm volatile("mma.sync.aligned.m16n8k16.row.col.f32.bf16.bf16.f32 "
        "{%0,%1,%2,%3}, {%4,%5,%6,%7}, {%8,%9}, {%0,%1,%2,%3};"
        : "+f"(d[0]), "+f"(d[1]), "+f"(d[2]), "+f"(d[3])
        : "r"(a[0]), "r"(a[1]), "r"(a[2]), "r"(a[3]), "r"(b0), "r"(b1));
}

// ---- bias assembly: bqkv | zeros(256) --------------------------------------
__global__ void pack_bias_kernel(const float* __restrict__ bqkv, float* __restrict__ bbig)
{
    int i = blockIdx.x*256 + threadIdx.x;
    if (i < NBIG) bbig[i] = (i < 1536) ? bqkv[i] : 0.f;
}

// ---- fp32 -> (bf16 hi, bf16 lo) split conversions ---------------------------
__device__ __forceinline__ void split4(float4 v, uint2& oh, uint2& ol)
{
    __nv_bfloat16 h0 = __float2bfloat16(v.x), h1 = __float2bfloat16(v.y);
    __nv_bfloat16 h2 = __float2bfloat16(v.z), h3 = __float2bfloat16(v.w);
    __nv_bfloat16 l0 = __float2bfloat16(v.x - __bfloat162float(h0));
    __nv_bfloat16 l1 = __float2bfloat16(v.y - __bfloat162float(h1));
    __nv_bfloat16 l2 = __float2bfloat16(v.z - __bfloat162float(h2));
    __nv_bfloat16 l3 = __float2bfloat16(v.w - __bfloat162float(h3));
    oh.x = (uint32_t)__bfloat16_as_ushort(h0) | ((uint32_t)__bfloat16_as_ushort(h1) << 16);
    oh.y = (uint32_t)__bfloat16_as_ushort(h2) | ((uint32_t)__bfloat16_as_ushort(h3) << 16);
    ol.x = (uint32_t)__bfloat16_as_ushort(l0) | ((uint32_t)__bfloat16_as_ushort(l1) << 16);
    ol.y = (uint32_t)__bfloat16_as_ushort(l2) | ((uint32_t)__bfloat16_as_ushort(l3) << 16);
}

__global__ void conv_x_kernel(const float4* __restrict__ x,
                              uint2* __restrict__ xh, uint2* __restrict__ xl)
{
    int i = blockIdx.x*256 + threadIdx.x;   // 262144 total
    uint2 oh, ol;
    split4(x[i], oh, ol);
    xh[i] = oh; xl[i] = ol;
}

__global__ void conv_w_kernel(const float* __restrict__ Wqkv,
                              const float* __restrict__ d1W1, const float* __restrict__ d2W1,
                              uint2* __restrict__ wh, uint2* __restrict__ wl)
{
    int i = blockIdx.x*256 + threadIdx.x;   // 229376 total (1792*128)
    int row = i >> 7, c4 = i & 127;
    const float* src = (row < 1536) ? (Wqkv + (size_t)row*512)
                     : (row < 1664) ? (d1W1 + (size_t)(row-1536)*512)
                                    : (d2W1 + (size_t)(row-1664)*512);
    uint2 oh, ol;
    split4(*(const float4*)(src + c4*4), oh, ol);
    wh[i] = oh; wl[i] = ol;
}

// ------- HMMA GEMM: C[m,n] = sum_k A[m,k]*B[n,k] + bias[n] -------------------
// 3-term bf16 split (AhBh + AhBl + AlBh), tile 128x128, BK=16, double-buffered.
// 8 warps, warp = 16 m-rows x 128 n-cols (16 n8 tiles).
// smem: [0,512) bias, then 2 buffers x {Ah,Al,Bh,Bl} each 128 rows x 48B.
#define MM_ARR  6144              // 128*48
#define MM_BUF  (4*MM_ARR)        // 24576
#define MM_SMEM (512 + 2*MM_BUF)  // 49664
__global__ void __launch_bounds__(256, 2) tgemm_mma(
    const __nv_bfloat16* __restrict__ Ah, const __nv_bfloat16* __restrict__ Al,
    const __nv_bfloat16* __restrict__ Bh, const __nv_bfloat16* __restrict__ Bl,
    float* __restrict__ C, int ldc, const float* __restrict__ bias, int K)
{
    extern __shared__ char smem[];
    float* sbias = (float*)smem;
    int tid = threadIdx.x, wid = tid >> 5, lane = tid & 31;
    int bn = blockIdx.x << 7, bm = blockIdx.y << 7;

    if (tid < 128) sbias[tid] = bias[bn + tid];

    // fill mapping: thread -> (row, k-half)
    int fr = tid >> 1, fh = tid & 1;
    uint32_t so = fr*48 + fh*16;
    const __nv_bfloat16* gAh = Ah + (size_t)(bm+fr)*K + fh*8;
    const __nv_bfloat16* gAl = Al + (size_t)(bm+fr)*K + fh*8;
    const __nv_bfloat16* gBh = Bh + (size_t)(bn+fr)*K + fh*8;
    const __nv_bfloat16* gBl = Bl + (size_t)(bn+fr)*K + fh*8;

    // prologue: chunk 0 -> buffer 0
    {
        char* d = smem + 512;
        *(uint4*)(d + so)            = *(const uint4*)gAh;
        *(uint4*)(d + MM_ARR   + so) = *(const uint4*)gAl;
        *(uint4*)(d + 2*MM_ARR + so) = *(const uint4*)gBh;
        *(uint4*)(d + 3*MM_ARR + so) = *(const uint4*)gBl;
    }
    __syncthreads();

    float acc[16][4];
    #pragma unroll
    for (int t = 0; t < 16; t++)
        #pragma unroll
        for (int j = 0; j < 4; j++) acc[t][j] = 0.f;

    // ldmatrix per-lane offsets
    uint32_t aoff = (uint32_t)((lane & 15)*48 + (lane >> 4)*16);
    int grp = lane >> 3;
    uint32_t boff = (uint32_t)(((lane & 7) + ((grp >> 1) << 3))*48 + (grp & 1)*16);
    uint32_t sb0 = smem_u32(smem) + 512;

    int nchunk = K >> 4;   // 32
    for (int c = 0; c < nchunk; ++c) {
        int cur = c & 1;
        uint4 vA0, vA1, vB0, vB1;
        bool more = (c + 1 < nchunk);
        if (more) {
            int ko = (c + 1) << 4;
            vA0 = *(const uint4*)(gAh + ko);
            vA1 = *(const uint4*)(gAl + ko);
            vB0 = *(const uint4*)(gBh + ko);
            vB1 = *(const uint4*)(gBl + ko);
        }
        uint32_t base = sb0 + cur*MM_BUF;
        uint32_t aAh[4], aAl[4];
        ldsm4(aAh, base + wid*768 + aoff);
        ldsm4(aAl, base + MM_ARR + wid*768 + aoff);
        #pragma unroll
        for (int nt2 = 0; nt2 < 8; nt2++) {
            uint32_t bh[4], bl[4];
            ldsm4(bh, base + 2*MM_ARR + nt2*768 + boff);
            ldsm4(bl, base + 3*MM_ARR + nt2*768 + boff);
            float* a0 = acc[nt2*2];
            float* a1 = acc[nt2*2 + 1];
            mma_bf16(a0, aAh, bh[0], bh[1]);
            mma_bf16(a1, aAh, bh[2], bh[3]);
            mma_bf16(a0, aAh, bl[0], bl[1]);
            mma_bf16(a1, aAh, bl[2], bl[3]);
            mma_bf16(a0, aAl, bh[0], bh[1]);
            mma_bf16(a1, aAl, bh[2], bh[3]);
        }
        if (more) {
            char* d = smem + 512 + (cur^1)*MM_BUF;
            *(uint4*)(d + so)            = vA0;
            *(uint4*)(d + MM_ARR   + so) = vA1;
            *(uint4*)(d + 2*MM_ARR + so) = vB0;
            *(uint4*)(d + 3*MM_ARR + so) = vB1;
            __syncthreads();
        }
    }

    // epilogue: d0/d1 = (row, col..col+1), d2/d3 = (row+8, col..col+1)
    int lane4 = lane & 3, lane8 = lane >> 2;
    #pragma unroll
    for (int nt = 0; nt < 16; nt++) {
        int n0 = (nt << 3) + (lane4 << 1);
        float b0 = sbias[n0], b1 = sbias[n0 + 1];
        int m0 = bm + wid*16 + lane8;
        float2 v0 = make_float2(acc[nt][0] + b0, acc[nt][1] + b1);
        float2 v1 = make_float2(acc[nt][2] + b0, acc[nt][3] + b1);
        *(float2*)&C[(size_t)m0*ldc + bn + n0]     = v0;
        *(float2*)&C[(size_t)(m0+8)*ldc + bn + n0] = v1;
    }
}

// ---------------- GEMM: BM=128, BN=64, BK=16, FFMA2 (R9 loop) ---------------
__global__ void __launch_bounds__(256, 2) gemm_nt(
    const float* __restrict__ A, int lda,
    const float* __restrict__ B, int ldb,
    float* __restrict__ C, int ldc,
    const float* __restrict__ bias,
    const float* __restrict__ resid, int ldr,
    int K, int mode)
{
    __shared__ float As[2][16][128];
    __shared__ float Bs[2][16][64];
    int bm = blockIdx.y << 7, bn = blockIdx.x << 6;
    int tid = threadIdx.x;
    int ty = tid >> 4, tx = tid & 15;
    int lr = tid >> 2, lk = (tid & 3) << 2;

    const float* Ap0 = A + (size_t)(bm + lr) * lda + lk;
    const float* Ap1 = Ap0 + (size_t)64 * lda;
    const float* Bp  = B + (size_t)(bn + lr) * ldb + lk;

    unsigned long long acc[4][4];
    #pragma unroll
    for (int i = 0; i < 4; i++)
        #pragma unroll
        for (int j = 0; j < 4; j++) acc[i][j] = 0ull;

    {
        float4 a0 = *(const float4*)Ap0;
        float4 a1 = *(const float4*)Ap1;
        float4 b0 = *(const float4*)Bp;
        As[0][lk+0][lr]    = a0.x; As[0][lk+1][lr]    = a0.y;
        As[0][lk+2][lr]    = a0.z; As[0][lk+3][lr]    = a0.w;
        As[0][lk+0][lr+64] = a1.x; As[0][lk+1][lr+64] = a1.y;
        As[0][lk+2][lr+64] = a1.z; As[0][lk+3][lr+64] = a1.w;
        Bs[0][lk+0][lr] = b0.x; Bs[0][lk+1][lr] = b0.y;
        Bs[0][lk+2][lr] = b0.z; Bs[0][lk+3][lr] = b0.w;
    }
    __syncthreads();

    int nk = K >> 4;
    for (int c = 0; c < nk; ++c) {
        int cur = c & 1;
        float4 na0, na1, nb0;
        bool more = (c + 1 < nk);
        if (more) {
            int ko = (c + 1) << 4;
            na0 = *(const float4*)(Ap0 + ko);
            na1 = *(const float4*)(Ap1 + ko);
            nb0 = *(const float4*)(Bp  + ko);
        }
        #pragma unroll
        for (int k = 0; k < 16; ++k) {
            ulonglong2 a01 = *(const ulonglong2*)&As[cur][k][ty*8];
            ulonglong2 a23 = *(const ulonglong2*)&As[cur][k][ty*8 + 4];
            float4 bf = *(const float4*)&Bs[cur][k][tx*4];
            unsigned long long ap[4] = {a01.x, a01.y, a23.x, a23.y};
            unsigned long long bd[4] = {bcast2(bf.x), bcast2(bf.y), bcast2(bf.z), bcast2(bf.w)};
            #pragma unroll
            for (int i = 0; i < 4; i++)
                #pragma unroll
                for (int j = 0; j < 4; j++)
                    acc[i][j] = ffma2(ap[i], bd[j], acc[i][j]);
        }
        if (more) {
            int nb = cur ^ 1;
            As[nb][lk+0][lr]    = na0.x; As[nb][lk+1][lr]    = na0.y;
            As[nb][lk+2][lr]    = na0.z; As[nb][lk+3][lr]    = na0.w;
            As[nb][lk+0][lr+64] = na1.x; As[nb][lk+1][lr+64] = na1.y;
            As[nb][lk+2][lr+64] = na1.z; As[nb][lk+3][lr+64] = na1.w;
            Bs[nb][lk+0][lr] = nb0.x; Bs[nb][lk+1][lr] = nb0.y;
            Bs[nb][lk+2][lr] = nb0.z; Bs[nb][lk+3][lr] = nb0.w;
            __syncthreads();
        }
    }

    int n = bn + tx*4;
    float4 bv = make_float4(0.f,0.f,0.f,0.f);
    if (bias) bv = *(const float4*)&bias[n];
    #pragma unroll
    for (int i2 = 0; i2 < 4; i2++) {
        float r0[4], r1[4];
        #pragma unroll
        for (int j = 0; j < 4; j++) unpack2(acc[i2][j], r0[j], r1[j]);
        int m0 = bm + ty*8 + i2*2;
        float4 v0 = make_float4(r0[0]+bv.x, r0[1]+bv.y, r0[2]+bv.z, r0[3]+bv.w);
        float4 v1 = make_float4(r1[0]+bv.x, r1[1]+bv.y, r1[2]+bv.z, r1[3]+bv.w);
        if (mode == 1) {
            float4 ra = *(const float4*)&resid[(size_t)m0*ldr + n];
            float4 rb = *(const float4*)&resid[(size_t)(m0+1)*ldr + n];
            v0.x = ra.x + fmaxf(v0.x,0.f); v0.y = ra.y + fmaxf(v0.y,0.f);
            v0.z = ra.z + fmaxf(v0.z,0.f); v0.w = ra.w + fmaxf(v0.w,0.f);
            v1.x = rb.x + fmaxf(v1.x,0.f); v1.y = rb.y + fmaxf(v1.y,0.f);
            v1.z = rb.z + fmaxf(v1.z,0.f); v1.w = rb.w + fmaxf(v1.w,0.f);
        }
        *(float4*)&C[(size_t)m0*ldc + n]     = v0;
        *(float4*)&C[(size_t)(m0+1)*ldc + n] = v1;
    }
}

// -------- x1 path: Gram (FFMA2 over e) -> softmax -> x1 = attn @ x ----------
__global__ void __launch_bounds__(256) x1_kernel(
    const float* __restrict__ x, float* __restrict__ a_out, float* __restrict__ xres)
{
    extern __shared__ float sm[];
    const int STR = 516;
    float* xs   = sm;
    float* sa   = xs + 64*STR;
    float* snrm = sa + 32*64;
    int b = blockIdx.x >> 1, half = blockIdx.x & 1;
    int tid = threadIdx.x;
    const float4* xb4 = (const float4*)(x + (size_t)b*SEQ*EMB);
    for (int i = tid; i < SEQ*128; i += 256) {
        int r = i >> 7, c4 = i & 127;
        *(float4*)&xs[r*STR + 4*c4] = xb4[i];
    }
    __syncthreads();

    {
        int t = tid >> 2, sub = tid & 3;
        float s = 0.f;
        #pragma unroll 8
        for (int j = 0; j < 128; j++) {
            float v = xs[t*STR + sub + 4*j];
            s = fmaf(v, v, s);
        }
        s += __shfl_xor_sync(0xffffffffu, s, 1);
        s += __shfl_xor_sync(0xffffffffu, s, 2);
        if (sub == 0) snrm[t] = s;
    }

    int w = tid>>5, lane = tid&31;
    int fl0 = w*4;
    int fbase = half*32;

    unsigned long long p0[4] = {0,0,0,0}, p1[4] = {0,0,0,0};
    for (int e4 = 0; e4 < 128; e4++) {
        ulonglong2 g0 = *(const ulonglong2*)&xs[lane*STR + 4*e4];
        ulonglong2 g1 = *(const ulonglong2*)&xs[(lane+32)*STR + 4*e4];
        #pragma unroll
        for (int i = 0; i < 4; i++) {
            ulonglong2 fv = *(const ulonglong2*)&xs[(fbase+fl0+i)*STR + 4*e4];
            p0[i] = ffma2(fv.x, g0.x, p0[i]);
            p0[i] = ffma2(fv.y, g0.y, p0[i]);
            p1[i] = ffma2(fv.x, g1.x, p1[i]);
            p1[i] = ffma2(fv.y, g1.y, p1[i]);
        }
    }
    #pragma unroll
    for (int i = 0; i < 4; i++) {
        sa[(fl0+i)*64 + lane]      = hsum2(p0[i]);
        sa[(fl0+i)*64 + lane + 32] = hsum2(p1[i]);
    }
    __syncthreads();

    const float invT = 1.f/13.544f;
    float* ab = a_out + (size_t)b*4096;
    #pragma unroll
    for (int i = 0; i < 4; i++) {
        int fl = fl0 + i, f = fbase + fl;
        float nf = snrm[f];
        float s0 = (2.f*sa[fl*64+lane]    - nf - snrm[lane])    * invT;
        float s1 = (2.f*sa[fl*64+lane+32] - nf - snrm[lane+32]) * invT;
        float m = fmaxf(s0, s1);
        for (int o = 16; o; o >>= 1) m = fmaxf(m, __shfl_xor_sync(0xffffffffu, m, o));
        float e0 = __expf(s0 - m), e1 = __expf(s1 - m);
        float sum = e0 + e1;
        for (int o = 16; o; o >>= 1) sum += __shfl_xor_sync(0xffffffffu, sum, o);
        float r = 1.f/sum; e0 *= r; e1 *= r;
        sa[fl*64+lane] = e0; sa[fl*64+lane+32] = e1;
        ab[f*64+lane] = e0;  ab[f*64+lane+32] = e1;
    }
    __syncwarp();

    for (int ec = 0; ec < 4; ec++) {
        float acc[4][4];
        #pragma unroll
        for (int i = 0; i < 4; i++) { acc[i][0]=acc[i][1]=acc[i][2]=acc[i][3]=0.f; }
        for (int g4 = 0; g4 < 16; g4++) {
            float sarr[4][4];
            #pragma unroll
            for (int i = 0; i < 4; i++)
                *(float4*)sarr[i] = *(const float4*)&sa[(fl0+i)*64 + 4*g4];
            #pragma unroll
            for (int jj = 0; jj < 4; jj++) {
                int g = 4*g4 + jj;
                float vv[4];
                #pragma unroll
                for (int j = 0; j < 4; j++) vv[j] = xs[g*STR + ec*128 + j*32 + lane];
                #pragma unroll
                for (int i = 0; i < 4; i++)
                    #pragma unroll
                    for (int j = 0; j < 4; j++)
                        acc[i][j] = fmaf(sarr[i][jj], vv[j], acc[i][j]);
            }
        }
        #pragma unroll
        for (int i = 0; i < 4; i++)
            #pragma unroll
            for (int j = 0; j < 4; j++)
                xres[(size_t)(b*SEQ + fbase + fl0 + i)*1024 + ec*128 + j*32 + lane] = acc[i][j];
    }
}

// -------------- MHA core: QK^T (FFMA2 over e), softmax, AV ------------------
__global__ void __launch_bounds__(256) mha_kernel(
    const float* __restrict__ qkv, float* __restrict__ attn_g, float* __restrict__ attno)
{
    extern __shared__ float sm[];
    const int STR = 132;
    float* qs = sm;
    float* ks = qs + 64*STR;
    float* vs = ks + 64*STR;
    float* sa = vs + 64*STR;
    int b = blockIdx.x >> 2, h = blockIdx.x & 3;
    int tid = threadIdx.x;
    const float* base = qkv + (size_t)b*SEQ*NBIG + h*128;
    for (int i = tid; i < 64*32; i += 256) {
        int r = i >> 5, c4 = (i & 31) << 2;
        const float* rp = base + (size_t)r*NBIG;
        *(float4*)&qs[r*STR+c4] = *(const float4*)&rp[c4];
        *(float4*)&ks[r*STR+c4] = *(const float4*)&rp[512 + c4];
        *(float4*)&vs[r*STR+c4] = *(const float4*)&rp[1024 + c4];
    }
    __syncthreads();
    int w = tid>>5, lane = tid&31, f0 = w*8;

    unsigned long long p0[8], p1[8];
    #pragma unroll
    for (int i = 0; i < 8; i++) { p0[i] = 0ull; p1[i] = 0ull; }
    for (int e4 = 0; e4 < 32; e4++) {
        ulonglong2 k0 = *(const ulonglong2*)&ks[lane*STR + 4*e4];
        ulonglong2 k1 = *(const ulonglong2*)&ks[(lane+32)*STR + 4*e4];
        #pragma unroll
        for (int i = 0; i < 8; i++) {
            ulonglong2 qv = *(const ulonglong2*)&qs[(f0+i)*STR + 4*e4];
            p0[i] = ffma2(qv.x, k0.x, p0[i]);
            p0[i] = ffma2(qv.y, k0.y, p0[i]);
            p1[i] = ffma2(qv.x, k1.x, p1[i]);
            p1[i] = ffma2(qv.y, k1.y, p1[i]);
        }
    }
    const float scale = 0.088388347648318447f;
    float* ab = attn_g + (size_t)(b*4 + h)*4096;
    #pragma unroll
    for (int i = 0; i < 8; i++) {
        float s0 = hsum2(p0[i])*scale, s1 = hsum2(p1[i])*scale;
        float m = fmaxf(s0, s1);
        for (int o = 16; o; o >>= 1) m = fmaxf(m, __shfl_xor_sync(0xffffffffu, m, o));
        float e0 = __expf(s0 - m), e1 = __expf(s1 - m);
        float sum = e0 + e1;
        for (int o = 16; o; o >>= 1) sum += __shfl_xor_sync(0xffffffffu, sum, o);
        float r = 1.f/sum; e0 *= r; e1 *= r;
        int f = f0 + i;
        sa[f*64+lane] = e0; sa[f*64+lane+32] = e1;
        ab[f*64+lane] = e0; ab[f*64+lane+32] = e1;
    }
    __syncwarp();
    float acc[8][4];
    #pragma unroll
    for (int i = 0; i < 8; i++) { acc[i][0]=acc[i][1]=acc[i][2]=acc[i][3]=0.f; }
    for (int g4 = 0; g4 < 16; g4++) {
        float sarr[8][4];
        #pragma unroll
        for (int i = 0; i < 8; i++)
            *(float4*)sarr[i] = *(const float4*)&sa[(f0+i)*64 + 4*g4];
        #pragma unroll
        for (int jj = 0; jj < 4; jj++) {
            int g = 4*g4 + jj;
            float vv[4];
            #pragma unroll
            for (int j = 0; j < 4; j++) vv[j] = vs[g*STR + j*32 + lane];
            #pragma unroll
            for (int i = 0; i < 8; i++)
                #pragma unroll
                for (int j = 0; j < 4; j++)
                    acc[i][j] = fmaf(sarr[i][jj], vv[j], acc[i][j]);
        }
    }
    #pragma unroll
    for (int i = 0; i < 8; i++)
        #pragma unroll
        for (int j = 0; j < 4; j++)
            attno[(size_t)(b*SEQ + f0 + i)*EMB + h*128 + j*32 + lane] = acc[i][j];
}

// ------------- layernorm over last dim (512) --------------------------------
__global__ void __launch_bounds__(128) ln_kernel(
    const float* __restrict__ in, const float* __restrict__ gw,
    const float* __restrict__ bw, float* __restrict__ out)
{
    int t = blockIdx.x, tid = threadIdx.x;
    const float* r = in + (size_t)t*EMB;
    float v[4];
    #pragma unroll
    for (int i = 0; i < 4; i++) v[i] = r[tid + i*128];
    float s  = v[0]+v[1]+v[2]+v[3];
    float s2 = v[0]*v[0]+v[1]*v[1]+v[2]*v[2]+v[3]*v[3];
    for (int o = 16; o; o >>= 1) {
        s  += __shfl_xor_sync(0xffffffffu, s,  o);
        s2 += __shfl_xor_sync(0xffffffffu, s2, o);
    }
    __shared__ float rs[4], rs2[4];
    int w = tid>>5, lane = tid&31;
    if (lane == 0) { rs[w] = s; rs2[w] = s2; }
    __syncthreads();
    s  = rs[0]+rs[1]+rs[2]+rs[3];
    s2 = rs2[0]+rs2[1]+rs2[2]+rs2[3];
    float mean = s*(1.f/512.f);
    float var  = s2*(1.f/512.f) - mean*mean;
    float inv  = rsqrtf(var + 1e-5f);
    #pragma unroll
    for (int i = 0; i < 4; i++) {
        int c = tid + i*128;
        out[(size_t)t*EMB + c] = (v[i]-mean)*inv*gw[c] + bw[c];
    }
}

// ------------- pair MLPs + fused head-mean ----------------------------------
__global__ void __launch_bounds__(256) pair_kernel(
    const float* __restrict__ ybig,
    const float* __restrict__ a1, const float* __restrict__ attn4,
    const float* __restrict__ b11, const float* __restrict__ w12, const float* __restrict__ b12,
    const float* __restrict__ b21, const float* __restrict__ w22, const float* __restrict__ b22,
    float* __restrict__ a2_out,
    float* __restrict__ o1, float* __restrict__ o2)
{
    extern __shared__ float sm[];
    float* sy1 = sm;
    float* sy2 = sy1 + 8192;
    float* sb1 = sy2 + 8192;
    float* sw1 = sb1 + 128;
    float* sb2 = sw1 + 128;
    float* sw2 = sb2 + 128;
    int b = blockIdx.x >> 2, q = blockIdx.x & 3;
    int tid = threadIdx.x;
    for (int i = tid; i < 8192; i += 256) {
        int r = i >> 7, c = i & 127;
        const float* rp = ybig + (size_t)(b*64 + r)*NBIG;
        sy1[i] = rp[1536 + c];
        sy2[i] = rp[1664 + c];
    }
    if (tid < 128) { sb1[tid]=b11[tid]; sw1[tid]=w12[tid]; sb2[tid]=b21[tid]; sw2[tid]=w22[tid]; }
    __syncthreads();
    float bias1 = b12[0], bias2 = b22[0];
    int w = tid>>5, lane = tid&31;
    int p0 = q*1024, p1 = p0 + 1024;
    const float* at = attn4 + (size_t)b*16384;
    for (int p = p0 + w; p < p1; p += 8) {
        int f = p >> 6, g = p & 63;
        float av1 = a1[(size_t)b*4096 + p];
        float av2 = 0.25f*(at[p] + at[p+4096] + at[p+8192] + at[p+12288]);
        const float* yg1 = sy1 + g*128; const float* yf1 = sy1 + f*128;
        const float* yg2 = sy2 + g*128; const float* yf2 = sy2 + f*128;
        float acc1 = 0.f, acc2 = 0.f;
        #pragma unroll
        for (int j = 0; j < 4; j++) {
            int c = j*32 + lane;
            float h1 = fmaf(av1, yg1[c]-yf1[c], sb1[c]);
            acc1 = fmaf(fmaxf(h1, 0.f), sw1[c], acc1);
            float h2 = fmaf(av2, yg2[c]-yf2[c], sb2[c]);
            acc2 = fmaf(fmaxf(h2, 0.f), sw2[c], acc2);
        }
        for (int o = 16; o; o >>= 1) {
            acc1 += __shfl_xor_sync(0xffffffffu, acc1, o);
            acc2 += __shfl_xor_sync(0xffffffffu, acc2, o);
        }
        if (lane == 0) {
            a2_out[(size_t)b*4096 + p] = av2;
            o1[(size_t)b*4096 + p] = fmaxf(acc1 + bias1, 0.f);
            o2[(size_t)b*4096 + p] = fmaxf(acc2 + bias2, 0.f);
        }
    }
}

// ---------------------------------------------------------------------------
extern "C" void kernel_launch(void* const* d_in, const int* in_sizes, int n_in,
                              void* d_out, int out_size)
{
    const float* x    = (const float*)d_in[0];
    const float* Wqkv = (const float*)d_in[1];
    const float* bqkv = (const float*)d_in[2];
    const float* Wo   = (const float*)d_in[3];
    const float* bo   = (const float*)d_in[4];
    const float* W1   = (const float*)d_in[5];
    const float* b1   = (const float*)d_in[6];
    const float* W2   = (const float*)d_in[7];
    const float* b2   = (const float*)d_in[8];
    const float* g1   = (const float*)d_in[9];
    const float* be1  = (const float*)d_in[10];
    const float* g2   = (const float*)d_in[11];
    const float* be2  = (const float*)d_in[12];
    const float* d1W1 = (const float*)d_in[13];
    const float* d1b1 = (const float*)d_in[14];
    const float* d1W2 = (const float*)d_in[15];
    const float* d1b2 = (const float*)d_in[16];
    const float* d2W1 = (const float*)d_in[17];
    const float* d2b1 = (const float*)d_in[18];
    const float* d2W2 = (const float*)d_in[19];
    const float* d2b2 = (const float*)d_in[20];

    float* out = (float*)d_out;
    float* A1 = out + 1048576;
    float* A2 = A1 + 131072;
    float* D1 = A2 + 131072;
    float* D2 = D1 + 131072;

    float *p_big, *p_bbig, *p_attn, *p_attno, *p_xres, *p_h, *p_ln1, *p_h2;
    __nv_bfloat16 *p_xh, *p_xl, *p_wh, *p_wl;
    cudaGetSymbolAddress((void**)&p_big,   g_big);
    cudaGetSymbolAddress((void**)&p_bbig,  g_bbig);
    cudaGetSymbolAddress((void**)&p_attn,  g_attn);
    cudaGetSymbolAddress((void**)&p_attno, g_attno);
    cudaGetSymbolAddress((void**)&p_xres,  g_xres);
    cudaGetSymbolAddress((void**)&p_h,     g_h);
    cudaGetSymbolAddress((void**)&p_ln1,   g_ln1);
    cudaGetSymbolAddress((void**)&p_h2,    g_h2);
    cudaGetSymbolAddress((void**)&p_xh,    g_xh);
    cudaGetSymbolAddress((void**)&p_xl,    g_xl);
    cudaGetSymbolAddress((void**)&p_wh,    g_wh);
    cudaGetSymbolAddress((void**)&p_wl,    g_wl);

    const int X1_SMEM   = (64*516 + 32*64 + 64) * 4;
    const int MHA_SMEM  = (3*64*132 + 4096) * 4;
    const int PAIR_SMEM = (2*8192 + 4*128) * 4;
    cudaFuncSetAttribute(x1_kernel,   cudaFuncAttributeMaxDynamicSharedMemorySize, X1_SMEM);
    cudaFuncSetAttribute(mha_kernel,  cudaFuncAttributeMaxDynamicSharedMemorySize, MHA_SMEM);
    cudaFuncSetAttribute(pair_kernel, cudaFuncAttributeMaxDynamicSharedMemorySize, PAIR_SMEM);
    cudaFuncSetAttribute(tgemm_mma,   cudaFuncAttributeMaxDynamicSharedMemorySize, MM_SMEM);

    static cudaStream_t s1 = nullptr, s2 = nullptr;
    static cudaEvent_t ev0, ev_x1, ev_mha, ev_pair, ev_w;
    if (!s1) {
        cudaStreamCreateWithFlags(&s1, cudaStreamNonBlocking);
        cudaStreamCreateWithFlags(&s2, cudaStreamNonBlocking);
        cudaEventCreateWithFlags(&ev0,     cudaEventDisableTiming);
        cudaEventCreateWithFlags(&ev_x1,   cudaEventDisableTiming);
        cudaEventCreateWithFlags(&ev_mha,  cudaEventDisableTiming);
        cudaEventCreateWithFlags(&ev_pair, cudaEventDisableTiming);
        cudaEventCreateWithFlags(&ev_w,    cudaEventDisableTiming);
    }

    // fork
    cudaEventRecord(ev0, 0);
    cudaStreamWaitEvent(s1, ev0, 0);
    cudaStreamWaitEvent(s2, ev0, 0);

    // branch s1: x1 path (depends only on x)
    x1_kernel<<<64, 256, X1_SMEM, s1>>>(x, A1, p_xres);
    cudaEventRecord(ev_x1, s1);

    // branch s2: weight conversion + bias pack (weight-only)
    conv_w_kernel<<<896, 256, 0, s2>>>(Wqkv, d1W1, d2W1, (uint2*)p_wh, (uint2*)p_wl);
    pack_bias_kernel<<<7, 256, 0, s2>>>(bqkv, p_bbig);
    cudaEventRecord(ev_w, s2);

    // main: x split conversion -> HMMA GEMM -> MHA
    conv_x_kernel<<<1024, 256>>>((const float4*)x, (uint2*)p_xh, (uint2*)p_xl);
    cudaStreamWaitEvent(0, ev_w, 0);
    tgemm_mma<<<dim3(NBIG/128, NTOK/128), 256, MM_SMEM>>>(
        p_xh, p_xl, p_wh, p_wl, p_big, NBIG, p_bbig, 512);
    mha_kernel<<<128, 256, MHA_SMEM>>>(p_big, p_attn, p_attno);
    cudaEventRecord(ev_mha, 0);

    // branch s2: pair MLPs (+fused head-mean)
    cudaStreamWaitEvent(s2, ev_mha, 0);
    cudaStreamWaitEvent(s2, ev_x1, 0);
    pair_kernel<<<128, 256, PAIR_SMEM, s2>>>(p_big, A1, p_attn,
                                             d1b1, d1W2, d1b2, d2b1, d2W2, d2b2,
                                             A2, D1, D2);
    cudaEventRecord(ev_pair, s2);

    // main: out-proj, join x1, fc1 -> LN1 -> fc2 -> LN2
    gemm_nt<<<dim3(8, 16), 256>>>(p_attno, 512, Wo, 512, p_xres + 512, 1024,
                                  bo, nullptr, 0, 512, 0);
    cudaStreamWaitEvent(0, ev_x1, 0);
    gemm_nt<<<dim3(8, 16), 256>>>(p_xres, 1024, W1, 1024, p_h, 512,
                                  b1, x, 512, 1024, 1);
    ln_kernel<<<2048, 128>>>(p_h, g1, be1, p_ln1);
    gemm_nt<<<dim3(8, 16), 256>>>(p_ln1, 512, W2, 512, p_h2, 512,
                                  b2, p_ln1, 512, 512, 1);
    ln_kernel<<<2048, 128>>>(p_h2, g2, be2, out);

    // join s2
    cudaStreamWaitEvent(0, ev_pair, 0);
}

// round 13
// speedup vs baseline: 1.4124x; 1.1872x over previous
#include <cuda_runtime.h>
#include <cuda_bf16.h>
#include <cstdint>

// Problem constants
#define NB 32
#define SEQ 64
#define EMB 512
#define NH 4
#define NTOK (NB*SEQ)          // 2048
#define NBIG 1792              // 1536 (qkv) + 128 (d1W1) + 128 (d2W1)

// ---------------- device scratch (no runtime alloc allowed) ----------------
__device__ float g_big  [NTOK*NBIG];     // qkv | y1 | y2
__device__ float g_bbig [NBIG];
__device__ float g_attn [NB*NH*SEQ*SEQ];
__device__ float g_h    [NTOK*EMB];
__device__ float g_ln1  [NTOK*EMB];
__device__ float g_h2   [NTOK*EMB];
__device__ __align__(16) __nv_bfloat16 g_xh[NTOK*EMB];
__device__ __align__(16) __nv_bfloat16 g_xl[NTOK*EMB];
__device__ __align__(16) __nv_bfloat16 g_wh[NBIG*EMB];
__device__ __align__(16) __nv_bfloat16 g_wl[NBIG*EMB];
__device__ __align__(16) __nv_bfloat16 g_attnoh[NTOK*EMB];
__device__ __align__(16) __nv_bfloat16 g_attnol[NTOK*EMB];
__device__ __align__(16) __nv_bfloat16 g_xresh[NTOK*1024];
__device__ __align__(16) __nv_bfloat16 g_xresl[NTOK*1024];
__device__ __align__(16) __nv_bfloat16 g_ln1h[NTOK*EMB];
__device__ __align__(16) __nv_bfloat16 g_ln1l[NTOK*EMB];
__device__ __align__(16) __nv_bfloat16 g_woh[EMB*EMB];
__device__ __align__(16) __nv_bfloat16 g_wol[EMB*EMB];
__device__ __align__(16) __nv_bfloat16 g_w1h[EMB*1024];
__device__ __align__(16) __nv_bfloat16 g_w1l[EMB*1024];
__device__ __align__(16) __nv_bfloat16 g_w2h[EMB*EMB];
__device__ __align__(16) __nv_bfloat16 g_w2l[EMB*EMB];

// ---------------- packed-fp32 helpers (FFMA2 via PTX) -----------------------
__device__ __forceinline__ unsigned long long ffma2(
    unsigned long long a, unsigned long long b, unsigned long long c)
{
    unsigned long long d;
    asm("fma.rn.f32x2 %0, %1, %2, %3;" : "=l"(d) : "l"(a), "l"(b), "l"(c));
    return d;
}
__device__ __forceinline__ float hsum2(unsigned long long d)
{
    float lo, hi;
    asm("mov.b64 {%0, %1}, %2;" : "=f"(lo), "=f"(hi) : "l"(d));
    return lo + hi;
}

// ---------------- mma.sync helpers ------------------------------------------
__device__ __forceinline__ uint32_t smem_u32(const void* p)
{
    uint32_t a;
    asm("{ .reg .u64 t; cvta.to.shared.u64 t, %1; cvt.u32.u64 %0, t; }" : "=r"(a) : "l"(p));
    return a;
}
__device__ __forceinline__ void ldsm4(uint32_t* r, uint32_t addr)
{
    asm volatile("ldmatrix.sync.aligned.m8n8.x4.shared.b16 {%0,%1,%2,%3}, [%4];"
        : "=r"(r[0]), "=r"(r[1]), "=r"(r[2]), "=r"(r[3]) : "r"(addr));
}
__device__ __forceinline__ void mma_bf16(float* d, const uint32_t* a, uint32_t b0, uint32_t b1)
{
    asm volatile("mma.sync.aligned.m16n8k16.row.col.f32.bf16.bf16.f32 "
        "{%0,%1,%2,%3}, {%4,%5,%6,%7}, {%8,%9}, {%0,%1,%2,%3};"
        : "+f"(d[0]), "+f"(d[1]), "+f"(d[2]), "+f"(d[3])
        : "r"(a[0]), "r"(a[1]), "r"(a[2]), "r"(a[3]), "r"(b0), "r"(b1));
}

// ---- bf16 split helpers -----------------------------------------------------
__device__ __forceinline__ void splitbf(float v, __nv_bfloat16& h, __nv_bfloat16& l)
{
    h = __float2bfloat16(v);
    l = __float2bfloat16(v - __bfloat162float(h));
}
__device__ __forceinline__ void split2pack(float a, float b, uint32_t& hh, uint32_t& ll)
{
    __nv_bfloat16 ha, la, hb, lb;
    splitbf(a, ha, la);
    splitbf(b, hb, lb);
    hh = (uint32_t)__bfloat16_as_ushort(ha) | ((uint32_t)__bfloat16_as_ushort(hb) << 16);
    ll = (uint32_t)__bfloat16_as_ushort(la) | ((uint32_t)__bfloat16_as_ushort(lb) << 16);
}
__device__ __forceinline__ void split4(float4 v, uint2& oh, uint2& ol)
{
    split2pack(v.x, v.y, oh.x, ol.x);
    split2pack(v.z, v.w, oh.y, ol.y);
}

// ---- bias assembly: bqkv | zeros(256) --------------------------------------
__global__ void pack_bias_kernel(const float* __restrict__ bqkv, float* __restrict__ bbig)
{
    int i = blockIdx.x*256 + threadIdx.x;
    if (i < NBIG) bbig[i] = (i < 1536) ? bqkv[i] : 0.f;
}

// ---- fp32 -> (bf16 hi, bf16 lo) split conversions ---------------------------
__global__ void conv_x_kernel(const float4* __restrict__ x,
                              uint2* __restrict__ xh, uint2* __restrict__ xl)
{
    int i = blockIdx.x*256 + threadIdx.x;   // 262144 total
    uint2 oh, ol;
    split4(x[i], oh, ol);
    xh[i] = oh; xl[i] = ol;
}

__global__ void conv_w_kernel(const float* __restrict__ Wqkv,
                              const float* __restrict__ d1W1, const float* __restrict__ d2W1,
                              uint2* __restrict__ wh, uint2* __restrict__ wl)
{
    int i = blockIdx.x*256 + threadIdx.x;   // 229376 total (1792*128)
    int row = i >> 7, c4 = i & 127;
    const float* src = (row < 1536) ? (Wqkv + (size_t)row*512)
                     : (row < 1664) ? (d1W1 + (size_t)(row-1536)*512)
                                    : (d2W1 + (size_t)(row-1664)*512);
    uint2 oh, ol;
    split4(*(const float4*)(src + c4*4), oh, ol);
    wh[i] = oh; wl[i] = ol;
}

// generic weight split (n4 float4 elements)
__global__ void conv_wgen_kernel(const float4* __restrict__ src,
                                 uint2* __restrict__ h, uint2* __restrict__ l)
{
    int i = blockIdx.x*256 + threadIdx.x;
    uint2 oh, ol;
    split4(src[i], oh, ol);
    h[i] = oh; l[i] = ol;
}

// ------- HMMA GEMM: C[m,n] = epi(sum_k A[m,k]*B[n,k] + bias[n]) --------------
// 3-term bf16 split (AhBh + AhBl + AlBh), tile 128x128, BK=16, double-buffered.
// 8 warps, warp = 16 m-rows x 128 n-cols (16 n8 tiles).
// mode 0: C(fp32) = acc + bias
// mode 1: (Ch,Cl)(bf16 split) = acc + bias
// mode 2: C(fp32) = resid + relu(acc + bias)
#define MM_ARR  6144              // 128*48
#define MM_BUF  (4*MM_ARR)        // 24576
#define MM_SMEM (512 + 2*MM_BUF)  // 49664
__global__ void __launch_bounds__(256, 2) tgemm_mma(
    const __nv_bfloat16* __restrict__ Ah, const __nv_bfloat16* __restrict__ Al, int lda,
    const __nv_bfloat16* __restrict__ Bh, const __nv_bfloat16* __restrict__ Bl, int ldb,
    float* __restrict__ C, int ldc,
    __nv_bfloat16* __restrict__ Ch, __nv_bfloat16* __restrict__ Cl, int ldc2,
    const float* __restrict__ bias,
    const float* __restrict__ resid, int ldr,
    int K, int mode)
{
    extern __shared__ char smem[];
    float* sbias = (float*)smem;
    int tid = threadIdx.x, wid = tid >> 5, lane = tid & 31;
    int bn = blockIdx.x << 7, bm = blockIdx.y << 7;

    if (tid < 128) sbias[tid] = bias[bn + tid];

    // fill mapping: thread -> (row, k-half)
    int fr = tid >> 1, fh = tid & 1;
    uint32_t so = fr*48 + fh*16;
    const __nv_bfloat16* gAh = Ah + (size_t)(bm+fr)*lda + fh*8;
    const __nv_bfloat16* gAl = Al + (size_t)(bm+fr)*lda + fh*8;
    const __nv_bfloat16* gBh = Bh + (size_t)(bn+fr)*ldb + fh*8;
    const __nv_bfloat16* gBl = Bl + (size_t)(bn+fr)*ldb + fh*8;

    // prologue: chunk 0 -> buffer 0
    {
        char* d = smem + 512;
        *(uint4*)(d + so)            = *(const uint4*)gAh;
        *(uint4*)(d + MM_ARR   + so) = *(const uint4*)gAl;
        *(uint4*)(d + 2*MM_ARR + so) = *(const uint4*)gBh;
        *(uint4*)(d + 3*MM_ARR + so) = *(const uint4*)gBl;
    }
    __syncthreads();

    float acc[16][4];
    #pragma unroll
    for (int t = 0; t < 16; t++)
        #pragma unroll
        for (int j = 0; j < 4; j++) acc[t][j] = 0.f;

    // ldmatrix per-lane offsets
    uint32_t aoff = (uint32_t)((lane & 15)*48 + (lane >> 4)*16);
    int grp = lane >> 3;
    uint32_t boff = (uint32_t)(((lane & 7) + ((grp >> 1) << 3))*48 + (grp & 1)*16);
    uint32_t sb0 = smem_u32(smem) + 512;

    int nchunk = K >> 4;
    for (int c = 0; c < nchunk; ++c) {
        int cur = c & 1;
        uint4 vA0, vA1, vB0, vB1;
        bool more = (c + 1 < nchunk);
        if (more) {
            int ko = (c + 1) << 4;
            vA0 = *(const uint4*)(gAh + ko);
            vA1 = *(const uint4*)(gAl + ko);
            vB0 = *(const uint4*)(gBh + ko);
            vB1 = *(const uint4*)(gBl + ko);
        }
        uint32_t base = sb0 + cur*MM_BUF;
        uint32_t aAh[4], aAl[4];
        ldsm4(aAh, base + wid*768 + aoff);
        ldsm4(aAl, base + MM_ARR + wid*768 + aoff);
        #pragma unroll
        for (int nt2 = 0; nt2 < 8; nt2++) {
            uint32_t bh[4], bl[4];
            ldsm4(bh, base + 2*MM_ARR + nt2*768 + boff);
            ldsm4(bl, base + 3*MM_ARR + nt2*768 + boff);
            float* a0 = acc[nt2*2];
            float* a1 = acc[nt2*2 + 1];
            mma_bf16(a0, aAh, bh[0], bh[1]);
            mma_bf16(a1, aAh, bh[2], bh[3]);
            mma_bf16(a0, aAh, bl[0], bl[1]);
            mma_bf16(a1, aAh, bl[2], bl[3]);
            mma_bf16(a0, aAl, bh[0], bh[1]);
            mma_bf16(a1, aAl, bh[2], bh[3]);
        }
        if (more) {
            char* d = smem + 512 + (cur^1)*MM_BUF;
            *(uint4*)(d + so)            = vA0;
            *(uint4*)(d + MM_ARR   + so) = vA1;
            *(uint4*)(d + 2*MM_ARR + so) = vB0;
            *(uint4*)(d + 3*MM_ARR + so) = vB1;
            __syncthreads();
        }
    }

    // epilogue: d0/d1 = (row, col..col+1), d2/d3 = (row+8, col..col+1)
    int lane4 = lane & 3, lane8 = lane >> 2;
    #pragma unroll
    for (int nt = 0; nt < 16; nt++) {
        int n0 = (nt << 3) + (lane4 << 1);
        float b0 = sbias[n0], b1 = sbias[n0 + 1];
        int m0 = bm + wid*16 + lane8;
        float v00 = acc[nt][0] + b0, v01 = acc[nt][1] + b1;
        float v10 = acc[nt][2] + b0, v11 = acc[nt][3] + b1;
        if (mode == 2) {
            float2 r0 = *(const float2*)&resid[(size_t)m0*ldr + bn + n0];
            float2 r1 = *(const float2*)&resid[(size_t)(m0+8)*ldr + bn + n0];
            v00 = r0.x + fmaxf(v00, 0.f); v01 = r0.y + fmaxf(v01, 0.f);
            v10 = r1.x + fmaxf(v10, 0.f); v11 = r1.y + fmaxf(v11, 0.f);
        }
        if (mode == 1) {
            uint32_t hh0, ll0, hh1, ll1;
            split2pack(v00, v01, hh0, ll0);
            split2pack(v10, v11, hh1, ll1);
            *(uint32_t*)&Ch[(size_t)m0*ldc2 + bn + n0]     = hh0;
            *(uint32_t*)&Cl[(size_t)m0*ldc2 + bn + n0]     = ll0;
            *(uint32_t*)&Ch[(size_t)(m0+8)*ldc2 + bn + n0] = hh1;
            *(uint32_t*)&Cl[(size_t)(m0+8)*ldc2 + bn + n0] = ll1;
        } else {
            *(float2*)&C[(size_t)m0*ldc + bn + n0]     = make_float2(v00, v01);
            *(float2*)&C[(size_t)(m0+8)*ldc + bn + n0] = make_float2(v10, v11);
        }
    }
}

// -------- x1 path: Gram (FFMA2 over e) -> softmax -> x1 (split bf16) --------
__global__ void __launch_bounds__(256) x1_kernel(
    const float* __restrict__ x, float* __restrict__ a_out,
    __nv_bfloat16* __restrict__ xresh, __nv_bfloat16* __restrict__ xresl)
{
    extern __shared__ float sm[];
    const int STR = 516;
    float* xs   = sm;
    float* sa   = xs + 64*STR;
    float* snrm = sa + 32*64;
    int b = blockIdx.x >> 1, half = blockIdx.x & 1;
    int tid = threadIdx.x;
    const float4* xb4 = (const float4*)(x + (size_t)b*SEQ*EMB);
    for (int i = tid; i < SEQ*128; i += 256) {
        int r = i >> 7, c4 = i & 127;
        *(float4*)&xs[r*STR + 4*c4] = xb4[i];
    }
    __syncthreads();

    {
        int t = tid >> 2, sub = tid & 3;
        float s = 0.f;
        #pragma unroll 8
        for (int j = 0; j < 128; j++) {
            float v = xs[t*STR + sub + 4*j];
            s = fmaf(v, v, s);
        }
        s += __shfl_xor_sync(0xffffffffu, s, 1);
        s += __shfl_xor_sync(0xffffffffu, s, 2);
        if (sub == 0) snrm[t] = s;
    }

    int w = tid>>5, lane = tid&31;
    int fl0 = w*4;
    int fbase = half*32;

    unsigned long long p0[4] = {0,0,0,0}, p1[4] = {0,0,0,0};
    for (int e4 = 0; e4 < 128; e4++) {
        ulonglong2 g0 = *(const ulonglong2*)&xs[lane*STR + 4*e4];
        ulonglong2 g1 = *(const ulonglong2*)&xs[(lane+32)*STR + 4*e4];
        #pragma unroll
        for (int i = 0; i < 4; i++) {
            ulonglong2 fv = *(const ulonglong2*)&xs[(fbase+fl0+i)*STR + 4*e4];
            p0[i] = ffma2(fv.x, g0.x, p0[i]);
            p0[i] = ffma2(fv.y, g0.y, p0[i]);
            p1[i] = ffma2(fv.x, g1.x, p1[i]);
            p1[i] = ffma2(fv.y, g1.y, p1[i]);
        }
    }
    #pragma unroll
    for (int i = 0; i < 4; i++) {
        sa[(fl0+i)*64 + lane]      = hsum2(p0[i]);
        sa[(fl0+i)*64 + lane + 32] = hsum2(p1[i]);
    }
    __syncthreads();

    const float invT = 1.f/13.544f;
    float* ab = a_out + (size_t)b*4096;
    #pragma unroll
    for (int i = 0; i < 4; i++) {
        int fl = fl0 + i, f = fbase + fl;
        float nf = snrm[f];
        float s0 = (2.f*sa[fl*64+lane]    - nf - snrm[lane])    * invT;
        float s1 = (2.f*sa[fl*64+lane+32] - nf - snrm[lane+32]) * invT;
        float m = fmaxf(s0, s1);
        for (int o = 16; o; o >>= 1) m = fmaxf(m, __shfl_xor_sync(0xffffffffu, m, o));
        float e0 = __expf(s0 - m), e1 = __expf(s1 - m);
        float sum = e0 + e1;
        for (int o = 16; o; o >>= 1) sum += __shfl_xor_sync(0xffffffffu, sum, o);
        float r = 1.f/sum; e0 *= r; e1 *= r;
        sa[fl*64+lane] = e0; sa[fl*64+lane+32] = e1;
        ab[f*64+lane] = e0;  ab[f*64+lane+32] = e1;
    }
    __syncwarp();

    for (int ec = 0; ec < 4; ec++) {
        float acc[4][4];
        #pragma unroll
        for (int i = 0; i < 4; i++) { acc[i][0]=acc[i][1]=acc[i][2]=acc[i][3]=0.f; }
        for (int g4 = 0; g4 < 16; g4++) {
            float sarr[4][4];
            #pragma unroll
            for (int i = 0; i < 4; i++)
                *(float4*)sarr[i] = *(const float4*)&sa[(fl0+i)*64 + 4*g4];
            #pragma unroll
            for (int jj = 0; jj < 4; jj++) {
                int g = 4*g4 + jj;
                float vv[4];
                #pragma unroll
                for (int j = 0; j < 4; j++) vv[j] = xs[g*STR + ec*128 + j*32 + lane];
                #pragma unroll
                for (int i = 0; i < 4; i++)
                    #pragma unroll
                    for (int j = 0; j < 4; j++)
                        acc[i][j] = fmaf(sarr[i][jj], vv[j], acc[i][j]);
            }
        }
        #pragma unroll
        for (int i = 0; i < 4; i++)
            #pragma unroll
            for (int j = 0; j < 4; j++) {
                size_t idx = (size_t)(b*SEQ + fbase + fl0 + i)*1024 + ec*128 + j*32 + lane;
                __nv_bfloat16 hh, ll;
                splitbf(acc[i][j], hh, ll);
                xresh[idx] = hh; xresl[idx] = ll;
            }
    }
}

// -------------- MHA core: QK^T (FFMA2 over e), softmax, AV ------------------
// attno written as split bf16 (feeds Wo HMMA GEMM).
__global__ void __launch_bounds__(256) mha_kernel(
    const float* __restrict__ qkv, float* __restrict__ attn_g,
    __nv_bfloat16* __restrict__ attnoh, __nv_bfloat16* __restrict__ attnol)
{
    extern __shared__ float sm[];
    const int STR = 132;
    float* qs = sm;
    float* ks = qs + 64*STR;
    float* vs = ks + 64*STR;
    float* sa = vs + 64*STR;
    int b = blockIdx.x >> 2, h = blockIdx.x & 3;
    int tid = threadIdx.x;
    const float* base = qkv + (size_t)b*SEQ*NBIG + h*128;
    for (int i = tid; i < 64*32; i += 256) {
        int r = i >> 5, c4 = (i & 31) << 2;
        const float* rp = base + (size_t)r*NBIG;
        *(float4*)&qs[r*STR+c4] = *(const float4*)&rp[c4];
        *(float4*)&ks[r*STR+c4] = *(const float4*)&rp[512 + c4];
        *(float4*)&vs[r*STR+c4] = *(const float4*)&rp[1024 + c4];
    }
    __syncthreads();
    int w = tid>>5, lane = tid&31, f0 = w*8;

    unsigned long long p0[8], p1[8];
    #pragma unroll
    for (int i = 0; i < 8; i++) { p0[i] = 0ull; p1[i] = 0ull; }
    for (int e4 = 0; e4 < 32; e4++) {
        ulonglong2 k0 = *(const ulonglong2*)&ks[lane*STR + 4*e4];
        ulonglong2 k1 = *(const ulonglong2*)&ks[(lane+32)*STR + 4*e4];
        #pragma unroll
        for (int i = 0; i < 8; i++) {
            ulonglong2 qv = *(const ulonglong2*)&qs[(f0+i)*STR + 4*e4];
            p0[i] = ffma2(qv.x, k0.x, p0[i]);
            p0[i] = ffma2(qv.y, k0.y, p0[i]);
            p1[i] = ffma2(qv.x, k1.x, p1[i]);
            p1[i] = ffma2(qv.y, k1.y, p1[i]);
        }
    }
    const float scale = 0.088388347648318447f;
    float* ab = attn_g + (size_t)(b*4 + h)*4096;
    #pragma unroll
    for (int i = 0; i < 8; i++) {
        float s0 = hsum2(p0[i])*scale, s1 = hsum2(p1[i])*scale;
        float m = fmaxf(s0, s1);
        for (int o = 16; o; o >>= 1) m = fmaxf(m, __shfl_xor_sync(0xffffffffu, m, o));
        float e0 = __expf(s0 - m), e1 = __expf(s1 - m);
        float sum = e0 + e1;
        for (int o = 16; o; o >>= 1) sum += __shfl_xor_sync(0xffffffffu, sum, o);
        float r = 1.f/sum; e0 *= r; e1 *= r;
        int f = f0 + i;
        sa[f*64+lane] = e0; sa[f*64+lane+32] = e1;
        ab[f*64+lane] = e0; ab[f*64+lane+32] = e1;
    }
    __syncwarp();
    float acc[8][4];
    #pragma unroll
    for (int i = 0; i < 8; i++) { acc[i][0]=acc[i][1]=acc[i][2]=acc[i][3]=0.f; }
    for (int g4 = 0; g4 < 16; g4++) {
        float sarr[8][4];
        #pragma unroll
        for (int i = 0; i < 8; i++)
            *(float4*)sarr[i] = *(const float4*)&sa[(f0+i)*64 + 4*g4];
        #pragma unroll
        for (int jj = 0; jj < 4; jj++) {
            int g = 4*g4 + jj;
            float vv[4];
            #pragma unroll
            for (int j = 0; j < 4; j++) vv[j] = vs[g*STR + j*32 + lane];
            #pragma unroll
            for (int i = 0; i < 8; i++)
                #pragma unroll
                for (int j = 0; j < 4; j++)
                    acc[i][j] = fmaf(sarr[i][jj], vv[j], acc[i][j]);
        }
    }
    #pragma unroll
    for (int i = 0; i < 8; i++)
        #pragma unroll
        for (int j = 0; j < 4; j++) {
            size_t idx = (size_t)(b*SEQ + f0 + i)*EMB + h*128 + j*32 + lane;
            __nv_bfloat16 hh, ll;
            splitbf(acc[i][j], hh, ll);
            attnoh[idx] = hh; attnol[idx] = ll;
        }
}

// ------------- layernorm over last dim (512), optional split out -------------
__global__ void __launch_bounds__(128) ln_kernel(
    const float* __restrict__ in, const float* __restrict__ gw,
    const float* __restrict__ bw, float* __restrict__ out,
    __nv_bfloat16* __restrict__ oh, __nv_bfloat16* __restrict__ ol)
{
    int t = blockIdx.x, tid = threadIdx.x;
    const float* r = in + (size_t)t*EMB;
    float v[4];
    #pragma unroll
    for (int i = 0; i < 4; i++) v[i] = r[tid + i*128];
    float s  = v[0]+v[1]+v[2]+v[3];
    float s2 = v[0]*v[0]+v[1]*v[1]+v[2]*v[2]+v[3]*v[3];
    for (int o = 16; o; o >>= 1) {
        s  += __shfl_xor_sync(0xffffffffu, s,  o);
        s2 += __shfl_xor_sync(0xffffffffu, s2, o);
    }
    __shared__ float rs[4], rs2[4];
    int w = tid>>5, lane = tid&31;
    if (lane == 0) { rs[w] = s; rs2[w] = s2; }
    __syncthreads();
    s  = rs[0]+rs[1]+rs[2]+rs[3];
    s2 = rs2[0]+rs2[1]+rs2[2]+rs2[3];
    float mean = s*(1.f/512.f);
    float var  = s2*(1.f/512.f) - mean*mean;
    float inv  = rsqrtf(var + 1e-5f);
    #pragma unroll
    for (int i = 0; i < 4; i++) {
        int c = tid + i*128;
        float ov = (v[i]-mean)*inv*gw[c] + bw[c];
        out[(size_t)t*EMB + c] = ov;
        if (oh) {
            __nv_bfloat16 hh, ll;
            splitbf(ov, hh, ll);
            oh[(size_t)t*EMB + c] = hh;
            ol[(size_t)t*EMB + c] = ll;
        }
    }
}

// ------------- pair MLPs + fused head-mean ----------------------------------
__global__ void __launch_bounds__(256) pair_kernel(
    const float* __restrict__ ybig,
    const float* __restrict__ a1, const float* __restrict__ attn4,
    const float* __restrict__ b11, const float* __restrict__ w12, const float* __restrict__ b12,
    const float* __restrict__ b21, const float* __restrict__ w22, const float* __restrict__ b22,
    float* __restrict__ a2_out,
    float* __restrict__ o1, float* __restrict__ o2)
{
    extern __shared__ float sm[];
    float* sy1 = sm;
    float* sy2 = sy1 + 8192;
    float* sb1 = sy2 + 8192;
    float* sw1 = sb1 + 128;
    float* sb2 = sw1 + 128;
    float* sw2 = sb2 + 128;
    int b = blockIdx.x >> 2, q = blockIdx.x & 3;
    int tid = threadIdx.x;
    for (int i = tid; i < 8192; i += 256) {
        int r = i >> 7, c = i & 127;
        const float* rp = ybig + (size_t)(b*64 + r)*NBIG;
        sy1[i] = rp[1536 + c];
        sy2[i] = rp[1664 + c];
    }
    if (tid < 128) { sb1[tid]=b11[tid]; sw1[tid]=w12[tid]; sb2[tid]=b21[tid]; sw2[tid]=w22[tid]; }
    __syncthreads();
    float bias1 = b12[0], bias2 = b22[0];
    int w = tid>>5, lane = tid&31;
    int p0 = q*1024, p1 = p0 + 1024;
    const float* at = attn4 + (size_t)b*16384;
    for (int p = p0 + w; p < p1; p += 8) {
        int f = p >> 6, g = p & 63;
        float av1 = a1[(size_t)b*4096 + p];
        float av2 = 0.25f*(at[p] + at[p+4096] + at[p+8192] + at[p+12288]);
        const float* yg1 = sy1 + g*128; const float* yf1 = sy1 + f*128;
        const float* yg2 = sy2 + g*128; const float* yf2 = sy2 + f*128;
        float acc1 = 0.f, acc2 = 0.f;
        #pragma unroll
        for (int j = 0; j < 4; j++) {
            int c = j*32 + lane;
            float h1 = fmaf(av1, yg1[c]-yf1[c], sb1[c]);
            acc1 = fmaf(fmaxf(h1, 0.f), sw1[c], acc1);
            float h2 = fmaf(av2, yg2[c]-yf2[c], sb2[c]);
            acc2 = fmaf(fmaxf(h2, 0.f), sw2[c], acc2);
        }
        for (int o = 16; o; o >>= 1) {
            acc1 += __shfl_xor_sync(0xffffffffu, acc1, o);
            acc2 += __shfl_xor_sync(0xffffffffu, acc2, o);
        }
        if (lane == 0) {
            a2_out[(size_t)b*4096 + p] = av2;
            o1[(size_t)b*4096 + p] = fmaxf(acc1 + bias1, 0.f);
            o2[(size_t)b*4096 + p] = fmaxf(acc2 + bias2, 0.f);
        }
    }
}

// ---------------------------------------------------------------------------
extern "C" void kernel_launch(void* const* d_in, const int* in_sizes, int n_in,
                              void* d_out, int out_size)
{
    const float* x    = (const float*)d_in[0];
    const float* Wqkv = (const float*)d_in[1];
    const float* bqkv = (const float*)d_in[2];
    const float* Wo   = (const float*)d_in[3];
    const float* bo   = (const float*)d_in[4];
    const float* W1   = (const float*)d_in[5];
    const float* b1   = (const float*)d_in[6];
    const float* W2   = (const float*)d_in[7];
    const float* b2   = (const float*)d_in[8];
    const float* g1   = (const float*)d_in[9];
    const float* be1  = (const float*)d_in[10];
    const float* g2   = (const float*)d_in[11];
    const float* be2  = (const float*)d_in[12];
    const float* d1W1 = (const float*)d_in[13];
    const float* d1b1 = (const float*)d_in[14];
    const float* d1W2 = (const float*)d_in[15];
    const float* d1b2 = (const float*)d_in[16];
    const float* d2W1 = (const float*)d_in[17];
    const float* d2b1 = (const float*)d_in[18];
    const float* d2W2 = (const float*)d_in[19];
    const float* d2b2 = (const float*)d_in[20];

    float* out = (float*)d_out;
    float* A1 = out + 1048576;
    float* A2 = A1 + 131072;
    float* D1 = A2 + 131072;
    float* D2 = D1 + 131072;

    float *p_big, *p_bbig, *p_attn, *p_h, *p_ln1, *p_h2;
    __nv_bfloat16 *p_xh, *p_xl, *p_wh, *p_wl;
    __nv_bfloat16 *p_attnoh, *p_attnol, *p_xresh, *p_xresl, *p_ln1h, *p_ln1l;
    __nv_bfloat16 *p_woh, *p_wol, *p_w1h, *p_w1l, *p_w2h, *p_w2l;
    cudaGetSymbolAddress((void**)&p_big,    g_big);
    cudaGetSymbolAddress((void**)&p_bbig,   g_bbig);
    cudaGetSymbolAddress((void**)&p_attn,   g_attn);
    cudaGetSymbolAddress((void**)&p_h,      g_h);
    cudaGetSymbolAddress((void**)&p_ln1,    g_ln1);
    cudaGetSymbolAddress((void**)&p_h2,     g_h2);
    cudaGetSymbolAddress((void**)&p_xh,     g_xh);
    cudaGetSymbolAddress((void**)&p_xl,     g_xl);
    cudaGetSymbolAddress((void**)&p_wh,     g_wh);
    cudaGetSymbolAddress((void**)&p_wl,     g_wl);
    cudaGetSymbolAddress((void**)&p_attnoh, g_attnoh);
    cudaGetSymbolAddress((void**)&p_attnol, g_attnol);
    cudaGetSymbolAddress((void**)&p_xresh,  g_xresh);
    cudaGetSymbolAddress((void**)&p_xresl,  g_xresl);
    cudaGetSymbolAddress((void**)&p_ln1h,   g_ln1h);
    cudaGetSymbolAddress((void**)&p_ln1l,   g_ln1l);
    cudaGetSymbolAddress((void**)&p_woh,    g_woh);
    cudaGetSymbolAddress((void**)&p_wol,    g_wol);
    cudaGetSymbolAddress((void**)&p_w1h,    g_w1h);
    cudaGetSymbolAddress((void**)&p_w1l,    g_w1l);
    cudaGetSymbolAddress((void**)&p_w2h,    g_w2h);
    cudaGetSymbolAddress((void**)&p_w2l,    g_w2l);

    const int X1_SMEM   = (64*516 + 32*64 + 64) * 4;
    const int MHA_SMEM  = (3*64*132 + 4096) * 4;
    const int PAIR_SMEM = (2*8192 + 4*128) * 4;
    cudaFuncSetAttribute(x1_kernel,   cudaFuncAttributeMaxDynamicSharedMemorySize, X1_SMEM);
    cudaFuncSetAttribute(mha_kernel,  cudaFuncAttributeMaxDynamicSharedMemorySize, MHA_SMEM);
    cudaFuncSetAttribute(pair_kernel, cudaFuncAttributeMaxDynamicSharedMemorySize, PAIR_SMEM);
    cudaFuncSetAttribute(tgemm_mma,   cudaFuncAttributeMaxDynamicSharedMemorySize, MM_SMEM);

    static cudaStream_t s1 = nullptr, s2 = nullptr;
    static cudaEvent_t ev0, ev_x1, ev_mha, ev_pair, ev_w, ev_w2;
    if (!s1) {
        cudaStreamCreateWithFlags(&s1, cudaStreamNonBlocking);
        cudaStreamCreateWithFlags(&s2, cudaStreamNonBlocking);
        cudaEventCreateWithFlags(&ev0,     cudaEventDisableTiming);
        cudaEventCreateWithFlags(&ev_x1,   cudaEventDisableTiming);
        cudaEventCreateWithFlags(&ev_mha,  cudaEventDisableTiming);
        cudaEventCreateWithFlags(&ev_pair, cudaEventDisableTiming);
        cudaEventCreateWithFlags(&ev_w,    cudaEventDisableTiming);
        cudaEventCreateWithFlags(&ev_w2,   cudaEventDisableTiming);
    }

    // fork
    cudaEventRecord(ev0, 0);
    cudaStreamWaitEvent(s1, ev0, 0);
    cudaStreamWaitEvent(s2, ev0, 0);

    // branch s1: x1 path (depends only on x) — writes split-bf16 xres[0:512)
    x1_kernel<<<64, 256, X1_SMEM, s1>>>(x, A1, p_xresh, p_xresl);
    cudaEventRecord(ev_x1, s1);

    // branch s2: weight conversions (weight-only, off critical path)
    conv_w_kernel<<<896, 256, 0, s2>>>(Wqkv, d1W1, d2W1, (uint2*)p_wh, (uint2*)p_wl);
    pack_bias_kernel<<<7, 256, 0, s2>>>(bqkv, p_bbig);
    cudaEventRecord(ev_w, s2);
    conv_wgen_kernel<<<256, 256, 0, s2>>>((const float4*)Wo, (uint2*)p_woh, (uint2*)p_wol);
    conv_wgen_kernel<<<512, 256, 0, s2>>>((const float4*)W1, (uint2*)p_w1h, (uint2*)p_w1l);
    conv_wgen_kernel<<<256, 256, 0, s2>>>((const float4*)W2, (uint2*)p_w2h, (uint2*)p_w2l);
    cudaEventRecord(ev_w2, s2);

    // main: x split conversion -> big HMMA GEMM -> MHA (split attno out)
    conv_x_kernel<<<1024, 256>>>((const float4*)x, (uint2*)p_xh, (uint2*)p_xl);
    cudaStreamWaitEvent(0, ev_w, 0);
    tgemm_mma<<<dim3(NBIG/128, NTOK/128), 256, MM_SMEM>>>(
        p_xh, p_xl, 512, p_wh, p_wl, 512,
        p_big, NBIG, nullptr, nullptr, 0, p_bbig, nullptr, 0, 512, 0);
    mha_kernel<<<128, 256, MHA_SMEM>>>(p_big, p_attn, p_attnoh, p_attnol);
    cudaEventRecord(ev_mha, 0);

    // branch s2: pair MLPs (+fused head-mean)
    cudaStreamWaitEvent(s2, ev_mha, 0);
    cudaStreamWaitEvent(s2, ev_x1, 0);
    pair_kernel<<<128, 256, PAIR_SMEM, s2>>>(p_big, A1, p_attn,
                                             d1b1, d1W2, d1b2, d2b1, d2W2, d2b2,
                                             A2, D1, D2);
    cudaEventRecord(ev_pair, s2);

    // main: Wo (HMMA, split out into xres[512:1024)) -> fc1 -> ln1 -> fc2 -> ln2
    cudaStreamWaitEvent(0, ev_w2, 0);
    tgemm_mma<<<dim3(4, 16), 256, MM_SMEM>>>(
        p_attnoh, p_attnol, 512, p_woh, p_wol, 512,
        nullptr, 0, p_xresh + 512, p_xresl + 512, 1024, bo, nullptr, 0, 512, 1);
    cudaStreamWaitEvent(0, ev_x1, 0);
    tgemm_mma<<<dim3(4, 16), 256, MM_SMEM>>>(
        p_xresh, p_xresl, 1024, p_w1h, p_w1l, 1024,
        p_h, 512, nullptr, nullptr, 0, b1, x, 512, 1024, 2);
    ln_kernel<<<2048, 128>>>(p_h, g1, be1, p_ln1, p_ln1h, p_ln1l);
    tgemm_mma<<<dim3(4, 16), 256, MM_SMEM>>>(
        p_ln1h, p_ln1l, 512, p_w2h, p_w2l, 512,
        p_h2, 512, nullptr, nullptr, 0, b2, p_ln1, 512, 512, 2);
    ln_kernel<<<2048, 128>>>(p_h2, g2, be2, out, nullptr, nullptr);

    // join s2
    cudaStreamWaitEvent(0, ev_pair, 0);
}

// round 14
// speedup vs baseline: 1.6568x; 1.1731x over previous
#include <cuda_runtime.h>
#include <cuda_bf16.h>
#include <cstdint>

// Problem constants
#define NB 32
#define SEQ 64
#define EMB 512
#define NH 4
#define NTOK (NB*SEQ)          // 2048
#define NBIG 1792              // 1536 (qkv) + 128 (d1W1) + 128 (d2W1)

// ---------------- device scratch (no runtime alloc allowed) ----------------
__device__ float g_big  [NTOK*NBIG];     // qkv | y1 | y2
__device__ float g_bbig [NBIG];
__device__ float g_attn [NB*NH*SEQ*SEQ];
__device__ float g_h    [NTOK*EMB];
__device__ float g_ln1  [NTOK*EMB];
__device__ float g_h2   [NTOK*EMB];
__device__ float g_M    [EMB*EMB];       // M = W1b @ Wo
__device__ float g_b1p  [EMB];           // b1 + W1b @ bo
__device__ __align__(16) __nv_bfloat16 g_xh[NTOK*EMB];
__device__ __align__(16) __nv_bfloat16 g_xl[NTOK*EMB];
__device__ __align__(16) __nv_bfloat16 g_wh[NBIG*EMB];
__device__ __align__(16) __nv_bfloat16 g_wl[NBIG*EMB];
__device__ __align__(16) __nv_bfloat16 g_xresh[NTOK*1024];
__device__ __align__(16) __nv_bfloat16 g_xresl[NTOK*1024];
__device__ __align__(16) __nv_bfloat16 g_ln1h[NTOK*EMB];
__device__ __align__(16) __nv_bfloat16 g_ln1l[NTOK*EMB];
__device__ __align__(16) __nv_bfloat16 g_w1ph[EMB*1024];  // [W1a | M] split hi
__device__ __align__(16) __nv_bfloat16 g_w1pl[EMB*1024];  // [W1a | M] split lo
__device__ __align__(16) __nv_bfloat16 g_w2h[EMB*EMB];
__device__ __align__(16) __nv_bfloat16 g_w2l[EMB*EMB];

// ---------------- packed-fp32 helpers (FFMA2 via PTX) -----------------------
__device__ __forceinline__ unsigned long long ffma2(
    unsigned long long a, unsigned long long b, unsigned long long c)
{
    unsigned long long d;
    asm("fma.rn.f32x2 %0, %1, %2, %3;" : "=l"(d) : "l"(a), "l"(b), "l"(c));
    return d;
}
__device__ __forceinline__ unsigned long long bcast2(float x)
{
    unsigned long long d;
    asm("mov.b64 %0, {%1, %1};" : "=l"(d) : "f"(x));
    return d;
}
__device__ __forceinline__ void unpack2(unsigned long long d, float& lo, float& hi)
{
    asm("mov.b64 {%0, %1}, %2;" : "=f"(lo), "=f"(hi) : "l"(d));
}
__device__ __forceinline__ float hsum2(unsigned long long d)
{
    float lo, hi;
    asm("mov.b64 {%0, %1}, %2;" : "=f"(lo), "=f"(hi) : "l"(d));
    return lo + hi;
}

// ---------------- mma.sync helpers ------------------------------------------
__device__ __forceinline__ uint32_t smem_u32(const void* p)
{
    uint32_t a;
    asm("{ .reg .u64 t; cvta.to.shared.u64 t, %1; cvt.u32.u64 %0, t; }" : "=r"(a) : "l"(p));
    return a;
}
__device__ __forceinline__ void ldsm4(uint32_t* r, uint32_t addr)
{
    asm volatile("ldmatrix.sync.aligned.m8n8.x4.shared.b16 {%0,%1,%2,%3}, [%4];"
        : "=r"(r[0]), "=r"(r[1]), "=r"(r[2]), "=r"(r[3]) : "r"(addr));
}
__device__ __forceinline__ void mma_bf16(float* d, const uint32_t* a, uint32_t b0, uint32_t b1)
{
    asm volatile("mma.sync.aligned.m16n8k16.row.col.f32.bf16.bf16.f32 "
        "{%0,%1,%2,%3}, {%4,%5,%6,%7}, {%8,%9}, {%0,%1,%2,%3};"
        : "+f"(d[0]), "+f"(d[1]), "+f"(d[2]), "+f"(d[3])
        : "r"(a[0]), "r"(a[1]), "r"(a[2]), "r"(a[3]), "r"(b0), "r"(b1));
}

// ---- bf16 split helpers -----------------------------------------------------
__device__ __forceinline__ void splitbf(float v, __nv_bfloat16& h, __nv_bfloat16& l)
{
    h = __float2bfloat16(v);
    l = __float2bfloat16(v - __bfloat162float(h));
}
__device__ __forceinline__ void split2pack(float a, float b, uint32_t& hh, uint32_t& ll)
{
    __nv_bfloat16 ha, la, hb, lb;
    splitbf(a, ha, la);
    splitbf(b, hb, lb);
    hh = (uint32_t)__bfloat16_as_ushort(ha) | ((uint32_t)__bfloat16_as_ushort(hb) << 16);
    ll = (uint32_t)__bfloat16_as_ushort(la) | ((uint32_t)__bfloat16_as_ushort(lb) << 16);
}
__device__ __forceinline__ void split4(float4 v, uint2& oh, uint2& ol)
{
    split2pack(v.x, v.y, oh.x, ol.x);
    split2pack(v.z, v.w, oh.y, ol.y);
}

// ---- bias assembly: bqkv | zeros(256) --------------------------------------
__global__ void pack_bias_kernel(const float* __restrict__ bqkv, float* __restrict__ bbig)
{
    int i = blockIdx.x*256 + threadIdx.x;
    if (i < NBIG) bbig[i] = (i < 1536) ? bqkv[i] : 0.f;
}

// ---- b1p[n] = b1[n] + sum_j W1b[n][j]*bo[j] --------------------------------
__global__ void __launch_bounds__(128) b1p_kernel(
    const float* __restrict__ W1, const float* __restrict__ b1,
    const float* __restrict__ bo, float* __restrict__ b1p)
{
    int w = threadIdx.x >> 5, lane = threadIdx.x & 31;
    int n = blockIdx.x*4 + w;
    const float* row = W1 + (size_t)n*1024 + 512;
    float s = 0.f;
    #pragma unroll
    for (int j = 0; j < 16; j++) {
        int c = lane + j*32;
        s = fmaf(row[c], bo[c], s);
    }
    for (int o = 16; o; o >>= 1) s += __shfl_xor_sync(0xffffffffu, s, o);
    if (lane == 0) b1p[n] = b1[n] + s;
}

// ---- fp32 -> (bf16 hi, bf16 lo) split conversions ---------------------------
__global__ void conv_x_kernel(const float4* __restrict__ x,
                              uint2* __restrict__ xh, uint2* __restrict__ xl)
{
    int i = blockIdx.x*256 + threadIdx.x;   // 262144 total
    uint2 oh, ol;
    split4(x[i], oh, ol);
    xh[i] = oh; xl[i] = ol;
}

__global__ void conv_w_kernel(const float* __restrict__ Wqkv,
                              const float* __restrict__ d1W1, const float* __restrict__ d2W1,
                              uint2* __restrict__ wh, uint2* __restrict__ wl)
{
    int i = blockIdx.x*256 + threadIdx.x;   // 229376 total (1792*128)
    int row = i >> 7, c4 = i & 127;
    const float* src = (row < 1536) ? (Wqkv + (size_t)row*512)
                     : (row < 1664) ? (d1W1 + (size_t)(row-1536)*512)
                                    : (d2W1 + (size_t)(row-1664)*512);
    uint2 oh, ol;
    split4(*(const float4*)(src + c4*4), oh, ol);
    wh[i] = oh; wl[i] = ol;
}

// generic weight split (n4 float4 elements)
__global__ void conv_wgen_kernel(const float4* __restrict__ src,
                                 uint2* __restrict__ h, uint2* __restrict__ l)
{
    int i = blockIdx.x*256 + threadIdx.x;
    uint2 oh, ol;
    split4(src[i], oh, ol);
    h[i] = oh; l[i] = ol;
}

// pack fc1 weight: W1p[n][k] = k<512 ? W1[n][k] : M[n][k-512], split bf16
__global__ void pack_w1_kernel(const float* __restrict__ W1, const float* __restrict__ M,
                               uint2* __restrict__ h, uint2* __restrict__ l)
{
    int i = blockIdx.x*256 + threadIdx.x;   // 131072 total (512*256 float4s)
    int n = i >> 8, c4 = i & 255;
    const float* src = (c4 < 128) ? (W1 + (size_t)n*1024 + c4*4)
                                  : (M + (size_t)n*512 + (c4-128)*4);
    uint2 oh, ol;
    split4(*(const float4*)src, oh, ol);
    h[i] = oh; l[i] = ol;
}

// ---------------- NN GEMM (FFMA2): C[m][n] = sum_j A[m][j]*B[j][n] ----------
// BM=128, BN=64, BK=16.  Used for M = W1b @ Wo (side stream, weight-only).
__global__ void __launch_bounds__(256, 2) gemm_nn(
    const float* __restrict__ A, int lda,
    const float* __restrict__ B, int ldb,
    float* __restrict__ C, int ldc, int K)
{
    __shared__ float As[2][16][128];
    __shared__ float Bs[2][16][64];
    int bm = blockIdx.y << 7, bn = blockIdx.x << 6;
    int tid = threadIdx.x;
    int ty = tid >> 4, tx = tid & 15;
    int lr = tid >> 2, lk = (tid & 3) << 2;
    int jr = tid >> 4, ncl = (tid & 15) << 2;

    const float* Ap0 = A + (size_t)(bm + lr) * lda + lk;
    const float* Ap1 = Ap0 + (size_t)64 * lda;
    const float* Bp  = B + (size_t)jr * ldb + bn + ncl;

    unsigned long long acc[4][4];
    #pragma unroll
    for (int i = 0; i < 4; i++)
        #pragma unroll
        for (int j = 0; j < 4; j++) acc[i][j] = 0ull;

    {
        float4 a0 = *(const float4*)Ap0;
        float4 a1 = *(const float4*)Ap1;
        float4 b0 = *(const float4*)Bp;
        As[0][lk+0][lr]    = a0.x; As[0][lk+1][lr]    = a0.y;
        As[0][lk+2][lr]    = a0.z; As[0][lk+3][lr]    = a0.w;
        As[0][lk+0][lr+64] = a1.x; As[0][lk+1][lr+64] = a1.y;
        As[0][lk+2][lr+64] = a1.z; As[0][lk+3][lr+64] = a1.w;
        *(float4*)&Bs[0][jr][ncl] = b0;
    }
    __syncthreads();

    int nk = K >> 4;
    for (int c = 0; c < nk; ++c) {
        int cur = c & 1;
        float4 na0, na1, nb0;
        bool more = (c + 1 < nk);
        if (more) {
            int ko = (c + 1) << 4;
            na0 = *(const float4*)(Ap0 + ko);
            na1 = *(const float4*)(Ap1 + ko);
            nb0 = *(const float4*)(Bp + (size_t)ko * ldb);
        }
        #pragma unroll
        for (int k = 0; k < 16; ++k) {
            ulonglong2 a01 = *(const ulonglong2*)&As[cur][k][ty*8];
            ulonglong2 a23 = *(const ulonglong2*)&As[cur][k][ty*8 + 4];
            float4 bf = *(const float4*)&Bs[cur][k][tx*4];
            unsigned long long ap[4] = {a01.x, a01.y, a23.x, a23.y};
            unsigned long long bd[4] = {bcast2(bf.x), bcast2(bf.y), bcast2(bf.z), bcast2(bf.w)};
            #pragma unroll
            for (int i = 0; i < 4; i++)
                #pragma unroll
                for (int j = 0; j < 4; j++)
                    acc[i][j] = ffma2(ap[i], bd[j], acc[i][j]);
        }
        if (more) {
            int nb = cur ^ 1;
            As[nb][lk+0][lr]    = na0.x; As[nb][lk+1][lr]    = na0.y;
            As[nb][lk+2][lr]    = na0.z; As[nb][lk+3][lr]    = na0.w;
            As[nb][lk+0][lr+64] = na1.x; As[nb][lk+1][lr+64] = na1.y;
            As[nb][lk+2][lr+64] = na1.z; As[nb][lk+3][lr+64] = na1.w;
            *(float4*)&Bs[nb][jr][ncl] = nb0;
            __syncthreads();
        }
    }

    int n = bn + tx*4;
    #pragma unroll
    for (int i2 = 0; i2 < 4; i2++) {
        float r0[4], r1[4];
        #pragma unroll
        for (int j = 0; j < 4; j++) unpack2(acc[i2][j], r0[j], r1[j]);
        int m0 = bm + ty*8 + i2*2;
        *(float4*)&C[(size_t)m0*ldc + n]     = make_float4(r0[0],r0[1],r0[2],r0[3]);
        *(float4*)&C[(size_t)(m0+1)*ldc + n] = make_float4(r1[0],r1[1],r1[2],r1[3]);
    }
}

// ------- HMMA GEMM: C[m,n] = epi(sum_k A[m,k]*B[n,k] + bias[n]) --------------
// 3-term bf16 split (AhBh + AhBl + AlBh), tile 128x128, BK=16, double-buffered.
// mode 0: C(fp32) = acc + bias
// mode 1: (Ch,Cl)(bf16 split) = acc + bias
// mode 2: C(fp32) = resid + relu(acc + bias)
#define MM_ARR  6144              // 128*48
#define MM_BUF  (4*MM_ARR)        // 24576
#define MM_SMEM (512 + 2*MM_BUF)  // 49664
__global__ void __launch_bounds__(256, 2) tgemm_mma(
    const __nv_bfloat16* __restrict__ Ah, const __nv_bfloat16* __restrict__ Al, int lda,
    const __nv_bfloat16* __restrict__ Bh, const __nv_bfloat16* __restrict__ Bl, int ldb,
    float* __restrict__ C, int ldc,
    __nv_bfloat16* __restrict__ Ch, __nv_bfloat16* __restrict__ Cl, int ldc2,
    const float* __restrict__ bias,
    const float* __restrict__ resid, int ldr,
    int K, int mode)
{
    extern __shared__ char smem[];
    float* sbias = (float*)smem;
    int tid = threadIdx.x, wid = tid >> 5, lane = tid & 31;
    int bn = blockIdx.x << 7, bm = blockIdx.y << 7;

    if (tid < 128) sbias[tid] = bias[bn + tid];

    int fr = tid >> 1, fh = tid & 1;
    uint32_t so = fr*48 + fh*16;
    const __nv_bfloat16* gAh = Ah + (size_t)(bm+fr)*lda + fh*8;
    const __nv_bfloat16* gAl = Al + (size_t)(bm+fr)*lda + fh*8;
    const __nv_bfloat16* gBh = Bh + (size_t)(bn+fr)*ldb + fh*8;
    const __nv_bfloat16* gBl = Bl + (size_t)(bn+fr)*ldb + fh*8;

    {
        char* d = smem + 512;
        *(uint4*)(d + so)            = *(const uint4*)gAh;
        *(uint4*)(d + MM_ARR   + so) = *(const uint4*)gAl;
        *(uint4*)(d + 2*MM_ARR + so) = *(const uint4*)gBh;
        *(uint4*)(d + 3*MM_ARR + so) = *(const uint4*)gBl;
    }
    __syncthreads();

    float acc[16][4];
    #pragma unroll
    for (int t = 0; t < 16; t++)
        #pragma unroll
        for (int j = 0; j < 4; j++) acc[t][j] = 0.f;

    uint32_t aoff = (uint32_t)((lane & 15)*48 + (lane >> 4)*16);
    int grp = lane >> 3;
    uint32_t boff = (uint32_t)(((lane & 7) + ((grp >> 1) << 3))*48 + (grp & 1)*16);
    uint32_t sb0 = smem_u32(smem) + 512;

    int nchunk = K >> 4;
    for (int c = 0; c < nchunk; ++c) {
        int cur = c & 1;
        uint4 vA0, vA1, vB0, vB1;
        bool more = (c + 1 < nchunk);
        if (more) {
            int ko = (c + 1) << 4;
            vA0 = *(const uint4*)(gAh + ko);
            vA1 = *(const uint4*)(gAl + ko);
            vB0 = *(const uint4*)(gBh + ko);
            vB1 = *(const uint4*)(gBl + ko);
        }
        uint32_t base = sb0 + cur*MM_BUF;
        uint32_t aAh[4], aAl[4];
        ldsm4(aAh, base + wid*768 + aoff);
        ldsm4(aAl, base + MM_ARR + wid*768 + aoff);
        #pragma unroll
        for (int nt2 = 0; nt2 < 8; nt2++) {
            uint32_t bh[4], bl[4];
            ldsm4(bh, base + 2*MM_ARR + nt2*768 + boff);
            ldsm4(bl, base + 3*MM_ARR + nt2*768 + boff);
            float* a0 = acc[nt2*2];
            float* a1 = acc[nt2*2 + 1];
            mma_bf16(a0, aAh, bh[0], bh[1]);
            mma_bf16(a1, aAh, bh[2], bh[3]);
            mma_bf16(a0, aAh, bl[0], bl[1]);
            mma_bf16(a1, aAh, bl[2], bl[3]);
            mma_bf16(a0, aAl, bh[0], bh[1]);
            mma_bf16(a1, aAl, bh[2], bh[3]);
        }
        if (more) {
            char* d = smem + 512 + (cur^1)*MM_BUF;
            *(uint4*)(d + so)            = vA0;
            *(uint4*)(d + MM_ARR   + so) = vA1;
            *(uint4*)(d + 2*MM_ARR + so) = vB0;
            *(uint4*)(d + 3*MM_ARR + so) = vB1;
            __syncthreads();
        }
    }

    int lane4 = lane & 3, lane8 = lane >> 2;
    #pragma unroll
    for (int nt = 0; nt < 16; nt++) {
        int n0 = (nt << 3) + (lane4 << 1);
        float b0 = sbias[n0], b1 = sbias[n0 + 1];
        int m0 = bm + wid*16 + lane8;
        float v00 = acc[nt][0] + b0, v01 = acc[nt][1] + b1;
        float v10 = acc[nt][2] + b0, v11 = acc[nt][3] + b1;
        if (mode == 2) {
            float2 r0 = *(const float2*)&resid[(size_t)m0*ldr + bn + n0];
            float2 r1 = *(const float2*)&resid[(size_t)(m0+8)*ldr + bn + n0];
            v00 = r0.x + fmaxf(v00, 0.f); v01 = r0.y + fmaxf(v01, 0.f);
            v10 = r1.x + fmaxf(v10, 0.f); v11 = r1.y + fmaxf(v11, 0.f);
        }
        if (mode == 1) {
            uint32_t hh0, ll0, hh1, ll1;
            split2pack(v00, v01, hh0, ll0);
            split2pack(v10, v11, hh1, ll1);
            *(uint32_t*)&Ch[(size_t)m0*ldc2 + bn + n0]     = hh0;
            *(uint32_t*)&Cl[(size_t)m0*ldc2 + bn + n0]     = ll0;
            *(uint32_t*)&Ch[(size_t)(m0+8)*ldc2 + bn + n0] = hh1;
            *(uint32_t*)&Cl[(size_t)(m0+8)*ldc2 + bn + n0] = ll1;
        } else {
            *(float2*)&C[(size_t)m0*ldc + bn + n0]     = make_float2(v00, v01);
            *(float2*)&C[(size_t)(m0+8)*ldc + bn + n0] = make_float2(v10, v11);
        }
    }
}

// -------- x1 path: Gram (FFMA2 over e) -> softmax -> x1 (split bf16) --------
__global__ void __launch_bounds__(256) x1_kernel(
    const float* __restrict__ x, float* __restrict__ a_out,
    __nv_bfloat16* __restrict__ xresh, __nv_bfloat16* __restrict__ xresl)
{
    extern __shared__ float sm[];
    const int STR = 516;
    float* xs   = sm;
    float* sa   = xs + 64*STR;
    float* snrm = sa + 32*64;
    int b = blockIdx.x >> 1, half = blockIdx.x & 1;
    int tid = threadIdx.x;
    const float4* xb4 = (const float4*)(x + (size_t)b*SEQ*EMB);
    for (int i = tid; i < SEQ*128; i += 256) {
        int r = i >> 7, c4 = i & 127;
        *(float4*)&xs[r*STR + 4*c4] = xb4[i];
    }
    __syncthreads();

    {
        int t = tid >> 2, sub = tid & 3;
        float s = 0.f;
        #pragma unroll 8
        for (int j = 0; j < 128; j++) {
            float v = xs[t*STR + sub + 4*j];
            s = fmaf(v, v, s);
        }
        s += __shfl_xor_sync(0xffffffffu, s, 1);
        s += __shfl_xor_sync(0xffffffffu, s, 2);
        if (sub == 0) snrm[t] = s;
    }

    int w = tid>>5, lane = tid&31;
    int fl0 = w*4;
    int fbase = half*32;

    unsigned long long p0[4] = {0,0,0,0}, p1[4] = {0,0,0,0};
    for (int e4 = 0; e4 < 128; e4++) {
        ulonglong2 g0 = *(const ulonglong2*)&xs[lane*STR + 4*e4];
        ulonglong2 g1 = *(const ulonglong2*)&xs[(lane+32)*STR + 4*e4];
        #pragma unroll
        for (int i = 0; i < 4; i++) {
            ulonglong2 fv = *(const ulonglong2*)&xs[(fbase+fl0+i)*STR + 4*e4];
            p0[i] = ffma2(fv.x, g0.x, p0[i]);
            p0[i] = ffma2(fv.y, g0.y, p0[i]);
            p1[i] = ffma2(fv.x, g1.x, p1[i]);
            p1[i] = ffma2(fv.y, g1.y, p1[i]);
        }
    }
    #pragma unroll
    for (int i = 0; i < 4; i++) {
        sa[(fl0+i)*64 + lane]      = hsum2(p0[i]);
        sa[(fl0+i)*64 + lane + 32] = hsum2(p1[i]);
    }
    __syncthreads();

    const float invT = 1.f/13.544f;
    float* ab = a_out + (size_t)b*4096;
    #pragma unroll
    for (int i = 0; i < 4; i++) {
        int fl = fl0 + i, f = fbase + fl;
        float nf = snrm[f];
        float s0 = (2.f*sa[fl*64+lane]    - nf - snrm[lane])    * invT;
        float s1 = (2.f*sa[fl*64+lane+32] - nf - snrm[lane+32]) * invT;
        float m = fmaxf(s0, s1);
        for (int o = 16; o; o >>= 1) m = fmaxf(m, __shfl_xor_sync(0xffffffffu, m, o));
        float e0 = __expf(s0 - m), e1 = __expf(s1 - m);
        float sum = e0 + e1;
        for (int o = 16; o; o >>= 1) sum += __shfl_xor_sync(0xffffffffu, sum, o);
        float r = 1.f/sum; e0 *= r; e1 *= r;
        sa[fl*64+lane] = e0; sa[fl*64+lane+32] = e1;
        ab[f*64+lane] = e0;  ab[f*64+lane+32] = e1;
    }
    __syncwarp();

    for (int ec = 0; ec < 4; ec++) {
        float acc[4][4];
        #pragma unroll
        for (int i = 0; i < 4; i++) { acc[i][0]=acc[i][1]=acc[i][2]=acc[i][3]=0.f; }
        for (int g4 = 0; g4 < 16; g4++) {
            float sarr[4][4];
            #pragma unroll
            for (int i = 0; i < 4; i++)
                *(float4*)sarr[i] = *(const float4*)&sa[(fl0+i)*64 + 4*g4];
            #pragma unroll
            for (int jj = 0; jj < 4; jj++) {
                int g = 4*g4 + jj;
                float vv[4];
                #pragma unroll
                for (int j = 0; j < 4; j++) vv[j] = xs[g*STR + ec*128 + j*32 + lane];
                #pragma unroll
                for (int i = 0; i < 4; i++)
                    #pragma unroll
                    for (int j = 0; j < 4; j++)
                        acc[i][j] = fmaf(sarr[i][jj], vv[j], acc[i][j]);
            }
        }
        #pragma unroll
        for (int i = 0; i < 4; i++)
            #pragma unroll
            for (int j = 0; j < 4; j++) {
                size_t idx = (size_t)(b*SEQ + fbase + fl0 + i)*1024 + ec*128 + j*32 + lane;
                __nv_bfloat16 hh, ll;
                splitbf(acc[i][j], hh, ll);
                xresh[idx] = hh; xresl[idx] = ll;
            }
    }
}

// -------------- MHA core: half-Q tile per block, 2 CTA/SM --------------------
// grid 256: block = (b, h, half).  attno (pre-Wo) written split bf16 into
// xres[512:1024) at stride ostride.
__global__ void __launch_bounds__(256) mha_kernel(
    const float* __restrict__ qkv, float* __restrict__ attn_g,
    __nv_bfloat16* __restrict__ oh, __nv_bfloat16* __restrict__ ol, int ostride)
{
    extern __shared__ float sm[];
    const int STR = 132;
    float* qs = sm;              // 32*132
    float* ks = qs + 32*STR;     // 64*132
    float* vs = ks + 64*STR;     // 64*132
    float* sa = vs + 64*STR;     // 32*64
    int bh = blockIdx.x >> 1, half = blockIdx.x & 1;
    int b = bh >> 2, h = bh & 3;
    int tid = threadIdx.x;
    const float* base = qkv + (size_t)b*SEQ*NBIG + h*128;
    for (int i = tid; i < 32*32; i += 256) {
        int r = i >> 5, c4 = (i & 31) << 2;
        const float* rp = base + (size_t)(half*32 + r)*NBIG;
        *(float4*)&qs[r*STR+c4] = *(const float4*)&rp[c4];
    }
    for (int i = tid; i < 64*32; i += 256) {
        int r = i >> 5, c4 = (i & 31) << 2;
        const float* rp = base + (size_t)r*NBIG;
        *(float4*)&ks[r*STR+c4] = *(const float4*)&rp[512 + c4];
        *(float4*)&vs[r*STR+c4] = *(const float4*)&rp[1024 + c4];
    }
    __syncthreads();
    int w = tid>>5, lane = tid&31, fl0 = w*4;

    unsigned long long p0[4] = {0,0,0,0}, p1[4] = {0,0,0,0};
    for (int e4 = 0; e4 < 32; e4++) {
        ulonglong2 k0 = *(const ulonglong2*)&ks[lane*STR + 4*e4];
        ulonglong2 k1 = *(const ulonglong2*)&ks[(lane+32)*STR + 4*e4];
        #pragma unroll
        for (int i = 0; i < 4; i++) {
            ulonglong2 qv = *(const ulonglong2*)&qs[(fl0+i)*STR + 4*e4];
            p0[i] = ffma2(qv.x, k0.x, p0[i]);
            p0[i] = ffma2(qv.y, k0.y, p0[i]);
            p1[i] = ffma2(qv.x, k1.x, p1[i]);
            p1[i] = ffma2(qv.y, k1.y, p1[i]);
        }
    }
    const float scale = 0.088388347648318447f;
    float* ab = attn_g + (size_t)(b*4 + h)*4096;
    #pragma unroll
    for (int i = 0; i < 4; i++) {
        int fl = fl0 + i, f = half*32 + fl;
        float s0 = hsum2(p0[i])*scale, s1 = hsum2(p1[i])*scale;
        float m = fmaxf(s0, s1);
        for (int o = 16; o; o >>= 1) m = fmaxf(m, __shfl_xor_sync(0xffffffffu, m, o));
        float e0 = __expf(s0 - m), e1 = __expf(s1 - m);
        float sum = e0 + e1;
        for (int o = 16; o; o >>= 1) sum += __shfl_xor_sync(0xffffffffu, sum, o);
        float r = 1.f/sum; e0 *= r; e1 *= r;
        sa[fl*64+lane] = e0; sa[fl*64+lane+32] = e1;
        ab[f*64+lane] = e0;  ab[f*64+lane+32] = e1;
    }
    __syncwarp();
    float acc[4][4];
    #pragma unroll
    for (int i = 0; i < 4; i++) { acc[i][0]=acc[i][1]=acc[i][2]=acc[i][3]=0.f; }
    for (int g4 = 0; g4 < 16; g4++) {
        float sarr[4][4];
        #pragma unroll
        for (int i = 0; i < 4; i++)
            *(float4*)sarr[i] = *(const float4*)&sa[(fl0+i)*64 + 4*g4];
        #pragma unroll
        for (int jj = 0; jj < 4; jj++) {
            int g = 4*g4 + jj;
            float vv[4];
            #pragma unroll
            for (int j = 0; j < 4; j++) vv[j] = vs[g*STR + j*32 + lane];
            #pragma unroll
            for (int i = 0; i < 4; i++)
                #pragma unroll
                for (int j = 0; j < 4; j++)
                    acc[i][j] = fmaf(sarr[i][jj], vv[j], acc[i][j]);
        }
    }
    #pragma unroll
    for (int i = 0; i < 4; i++)
        #pragma unroll
        for (int j = 0; j < 4; j++) {
            size_t idx = (size_t)(b*SEQ + half*32 + fl0 + i)*ostride + h*128 + j*32 + lane;
            __nv_bfloat16 hh, ll;
            splitbf(acc[i][j], hh, ll);
            oh[idx] = hh; ol[idx] = ll;
        }
}

// ------------- layernorm over last dim (512), optional split out -------------
__global__ void __launch_bounds__(128) ln_kernel(
    const float* __restrict__ in, const float* __restrict__ gw,
    const float* __restrict__ bw, float* __restrict__ out,
    __nv_bfloat16* __restrict__ oh, __nv_bfloat16* __restrict__ ol)
{
    int t = blockIdx.x, tid = threadIdx.x;
    const float* r = in + (size_t)t*EMB;
    float v[4];
    #pragma unroll
    for (int i = 0; i < 4; i++) v[i] = r[tid + i*128];
    float s  = v[0]+v[1]+v[2]+v[3];
    float s2 = v[0]*v[0]+v[1]*v[1]+v[2]*v[2]+v[3]*v[3];
    for (int o = 16; o; o >>= 1) {
        s  += __shfl_xor_sync(0xffffffffu, s,  o);
        s2 += __shfl_xor_sync(0xffffffffu, s2, o);
    }
    __shared__ float rs[4], rs2[4];
    int w = tid>>5, lane = tid&31;
    if (lane == 0) { rs[w] = s; rs2[w] = s2; }
    __syncthreads();
    s  = rs[0]+rs[1]+rs[2]+rs[3];
    s2 = rs2[0]+rs2[1]+rs2[2]+rs2[3];
    float mean = s*(1.f/512.f);
    float var  = s2*(1.f/512.f) - mean*mean;
    float inv  = rsqrtf(var + 1e-5f);
    #pragma unroll
    for (int i = 0; i < 4; i++) {
        int c = tid + i*128;
        float ov = (v[i]-mean)*inv*gw[c] + bw[c];
        out[(size_t)t*EMB + c] = ov;
        if (oh) {
            __nv_bfloat16 hh, ll;
            splitbf(ov, hh, ll);
            oh[(size_t)t*EMB + c] = hh;
            ol[(size_t)t*EMB + c] = ll;
        }
    }
}

// ------------- pair MLPs + fused head-mean ----------------------------------
__global__ void __launch_bounds__(256) pair_kernel(
    const float* __restrict__ ybig,
    const float* __restrict__ a1, const float* __restrict__ attn4,
    const float* __restrict__ b11, const float* __restrict__ w12, const float* __restrict__ b12,
    const float* __restrict__ b21, const float* __restrict__ w22, const float* __restrict__ b22,
    float* __restrict__ a2_out,
    float* __restrict__ o1, float* __restrict__ o2)
{
    extern __shared__ float sm[];
    float* sy1 = sm;
    float* sy2 = sy1 + 8192;
    float* sb1 = sy2 + 8192;
    float* sw1 = sb1 + 128;
    float* sb2 = sw1 + 128;
    float* sw2 = sb2 + 128;
    int b = blockIdx.x >> 2, q = blockIdx.x & 3;
    int tid = threadIdx.x;
    for (int i = tid; i < 8192; i += 256) {
        int r = i >> 7, c = i & 127;
        const float* rp = ybig + (size_t)(b*64 + r)*NBIG;
        sy1[i] = rp[1536 + c];
        sy2[i] = rp[1664 + c];
    }
    if (tid < 128) { sb1[tid]=b11[tid]; sw1[tid]=w12[tid]; sb2[tid]=b21[tid]; sw2[tid]=w22[tid]; }
    __syncthreads();
    float bias1 = b12[0], bias2 = b22[0];
    int w = tid>>5, lane = tid&31;
    int p0 = q*1024, p1 = p0 + 1024;
    const float* at = attn4 + (size_t)b*16384;
    for (int p = p0 + w; p < p1; p += 8) {
        int f = p >> 6, g = p & 63;
        float av1 = a1[(size_t)b*4096 + p];
        float av2 = 0.25f*(at[p] + at[p+4096] + at[p+8192] + at[p+12288]);
        const float* yg1 = sy1 + g*128; const float* yf1 = sy1 + f*128;
        const float* yg2 = sy2 + g*128; const float* yf2 = sy2 + f*128;
        float acc1 = 0.f, acc2 = 0.f;
        #pragma unroll
        for (int j = 0; j < 4; j++) {
            int c = j*32 + lane;
            float h1 = fmaf(av1, yg1[c]-yf1[c], sb1[c]);
            acc1 = fmaf(fmaxf(h1, 0.f), sw1[c], acc1);
            float h2 = fmaf(av2, yg2[c]-yf2[c], sb2[c]);
            acc2 = fmaf(fmaxf(h2, 0.f), sw2[c], acc2);
        }
        for (int o = 16; o; o >>= 1) {
            acc1 += __shfl_xor_sync(0xffffffffu, acc1, o);
            acc2 += __shfl_xor_sync(0xffffffffu, acc2, o);
        }
        if (lane == 0) {
            a2_out[(size_t)b*4096 + p] = av2;
            o1[(size_t)b*4096 + p] = fmaxf(acc1 + bias1, 0.f);
            o2[(size_t)b*4096 + p] = fmaxf(acc2 + bias2, 0.f);
        }
    }
}

// ---------------------------------------------------------------------------
extern "C" void kernel_launch(void* const* d_in, const int* in_sizes, int n_in,
                              void* d_out, int out_size)
{
    const float* x    = (const float*)d_in[0];
    const float* Wqkv = (const float*)d_in[1];
    const float* bqkv = (const float*)d_in[2];
    const float* Wo   = (const float*)d_in[3];
    const float* bo   = (const float*)d_in[4];
    const float* W1   = (const float*)d_in[5];
    const float* b1   = (const float*)d_in[6];
    const float* W2   = (const float*)d_in[7];
    const float* b2   = (const float*)d_in[8];
    const float* g1   = (const float*)d_in[9];
    const float* be1  = (const float*)d_in[10];
    const float* g2   = (const float*)d_in[11];
    const float* be2  = (const float*)d_in[12];
    const float* d1W1 = (const float*)d_in[13];
    const float* d1b1 = (const float*)d_in[14];
    const float* d1W2 = (const float*)d_in[15];
    const float* d1b2 = (const float*)d_in[16];
    const float* d2W1 = (const float*)d_in[17];
    const float* d2b1 = (const float*)d_in[18];
    const float* d2W2 = (const float*)d_in[19];
    const float* d2b2 = (const float*)d_in[20];

    float* out = (float*)d_out;
    float* A1 = out + 1048576;
    float* A2 = A1 + 131072;
    float* D1 = A2 + 131072;
    float* D2 = D1 + 131072;

    float *p_big, *p_bbig, *p_attn, *p_h, *p_ln1, *p_h2, *p_M, *p_b1p;
    __nv_bfloat16 *p_xh, *p_xl, *p_wh, *p_wl;
    __nv_bfloat16 *p_xresh, *p_xresl, *p_ln1h, *p_ln1l;
    __nv_bfloat16 *p_w1ph, *p_w1pl, *p_w2h, *p_w2l;
    cudaGetSymbolAddress((void**)&p_big,    g_big);
    cudaGetSymbolAddress((void**)&p_bbig,   g_bbig);
    cudaGetSymbolAddress((void**)&p_attn,   g_attn);
    cudaGetSymbolAddress((void**)&p_h,      g_h);
    cudaGetSymbolAddress((void**)&p_ln1,    g_ln1);
    cudaGetSymbolAddress((void**)&p_h2,     g_h2);
    cudaGetSymbolAddress((void**)&p_M,      g_M);
    cudaGetSymbolAddress((void**)&p_b1p,    g_b1p);
    cudaGetSymbolAddress((void**)&p_xh,     g_xh);
    cudaGetSymbolAddress((void**)&p_xl,     g_xl);
    cudaGetSymbolAddress((void**)&p_wh,     g_wh);
    cudaGetSymbolAddress((void**)&p_wl,     g_wl);
    cudaGetSymbolAddress((void**)&p_xresh,  g_xresh);
    cudaGetSymbolAddress((void**)&p_xresl,  g_xresl);
    cudaGetSymbolAddress((void**)&p_ln1h,   g_ln1h);
    cudaGetSymbolAddress((void**)&p_ln1l,   g_ln1l);
    cudaGetSymbolAddress((void**)&p_w1ph,   g_w1ph);
    cudaGetSymbolAddress((void**)&p_w1pl,   g_w1pl);
    cudaGetSymbolAddress((void**)&p_w2h,    g_w2h);
    cudaGetSymbolAddress((void**)&p_w2l,    g_w2l);

    const int X1_SMEM   = (64*516 + 32*64 + 64) * 4;
    const int MHA_SMEM  = (32*132 + 2*64*132 + 32*64) * 4;   // 92672
    const int PAIR_SMEM = (2*8192 + 4*128) * 4;
    cudaFuncSetAttribute(x1_kernel,   cudaFuncAttributeMaxDynamicSharedMemorySize, X1_SMEM);
    cudaFuncSetAttribute(mha_kernel,  cudaFuncAttributeMaxDynamicSharedMemorySize, MHA_SMEM);
    cudaFuncSetAttribute(pair_kernel, cudaFuncAttributeMaxDynamicSharedMemorySize, PAIR_SMEM);
    cudaFuncSetAttribute(tgemm_mma,   cudaFuncAttributeMaxDynamicSharedMemorySize, MM_SMEM);

    static cudaStream_t s1 = nullptr, s2 = nullptr;
    static cudaEvent_t ev0, ev_x1, ev_mha, ev_pair, ev_w, ev_w2;
    if (!s1) {
        cudaStreamCreateWithFlags(&s1, cudaStreamNonBlocking);
        cudaStreamCreateWithFlags(&s2, cudaStreamNonBlocking);
        cudaEventCreateWithFlags(&ev0,     cudaEventDisableTiming);
        cudaEventCreateWithFlags(&ev_x1,   cudaEventDisableTiming);
        cudaEventCreateWithFlags(&ev_mha,  cudaEventDisableTiming);
        cudaEventCreateWithFlags(&ev_pair, cudaEventDisableTiming);
        cudaEventCreateWithFlags(&ev_w,    cudaEventDisableTiming);
        cudaEventCreateWithFlags(&ev_w2,   cudaEventDisableTiming);
    }

    // fork
    cudaEventRecord(ev0, 0);
    cudaStreamWaitEvent(s1, ev0, 0);
    cudaStreamWaitEvent(s2, ev0, 0);

    // branch s1: x1 path (depends only on x) — writes split-bf16 xres[0:512)
    x1_kernel<<<64, 256, X1_SMEM, s1>>>(x, A1, p_xresh, p_xresl);
    cudaEventRecord(ev_x1, s1);

    // branch s2: weight-only precompute (fully off critical path)
    conv_w_kernel<<<896, 256, 0, s2>>>(Wqkv, d1W1, d2W1, (uint2*)p_wh, (uint2*)p_wl);
    pack_bias_kernel<<<7, 256, 0, s2>>>(bqkv, p_bbig);
    cudaEventRecord(ev_w, s2);
    gemm_nn<<<dim3(8, 4), 256, 0, s2>>>(W1 + 512, 1024, Wo, 512, p_M, 512, 512);
    b1p_kernel<<<128, 128, 0, s2>>>(W1, b1, bo, p_b1p);
    pack_w1_kernel<<<512, 256, 0, s2>>>(W1, p_M, (uint2*)p_w1ph, (uint2*)p_w1pl);
    conv_wgen_kernel<<<256, 256, 0, s2>>>((const float4*)W2, (uint2*)p_w2h, (uint2*)p_w2l);
    cudaEventRecord(ev_w2, s2);

    // main: x split conversion -> big HMMA GEMM -> MHA (split attno into xres)
    conv_x_kernel<<<1024, 256>>>((const float4*)x, (uint2*)p_xh, (uint2*)p_xl);
    cudaStreamWaitEvent(0, ev_w, 0);
    tgemm_mma<<<dim3(NBIG/128, NTOK/128), 256, MM_SMEM>>>(
        p_xh, p_xl, 512, p_wh, p_wl, 512,
        p_big, NBIG, nullptr, nullptr, 0, p_bbig, nullptr, 0, 512, 0);
    mha_kernel<<<256, 256, MHA_SMEM>>>(p_big, p_attn, p_xresh + 512, p_xresl + 512, 1024);
    cudaEventRecord(ev_mha, 0);

    // branch s2: pair MLPs (+fused head-mean)
    cudaStreamWaitEvent(s2, ev_mha, 0);
    cudaStreamWaitEvent(s2, ev_x1, 0);
    pair_kernel<<<128, 256, PAIR_SMEM, s2>>>(p_big, A1, p_attn,
                                             d1b1, d1W2, d1b2, d2b1, d2W2, d2b2,
                                             A2, D1, D2);
    cudaEventRecord(ev_pair, s2);

    // main: fc1 (Wo folded) -> ln1 -> fc2 -> ln2
    cudaStreamWaitEvent(0, ev_x1, 0);
    cudaStreamWaitEvent(0, ev_w2, 0);
    tgemm_mma<<<dim3(4, 16), 256, MM_SMEM>>>(
        p_xresh, p_xresl, 1024, p_w1ph, p_w1pl, 1024,
        p_h, 512, nullptr, nullptr, 0, p_b1p, x, 512, 1024, 2);
    ln_kernel<<<2048, 128>>>(p_h, g1, be1, p_ln1, p_ln1h, p_ln1l);
    tgemm_mma<<<dim3(4, 16), 256, MM_SMEM>>>(
        p_ln1h, p_ln1l, 512, p_w2h, p_w2l, 512,
        p_h2, 512, nullptr, nullptr, 0, b2, p_ln1, 512, 512, 2);
    ln_kernel<<<2048, 128>>>(p_h2, g2, be2, out, nullptr, nullptr);

    // join s2
    cudaStreamWaitEvent(0, ev_pair, 0);
}